// round 10
// baseline (speedup 1.0000x reference)
#include <cuda_runtime.h>
#include <cuda_bf16.h>
#include <cuda_fp16.h>
#include <math.h>
#include <stdint.h>

#define BB 64
#define FF 256
#define TT 1024
#define HH 1024
#define OO 512
#define NB 128   // persistent CTAs: 4 batch-row groups x 32 H-col tiles

// Scratch (allocation-free rule: __device__ globals)
__device__ float  g_Z[(size_t)TT * BB * HH];    // Z = x@Wx + b, later overwritten with states, [t][b][h]
__device__ __half g_ST2h[2][4][HH * 16];        // fp16 transposed state ping-pong, [buf][r-group][h][16 b]
__device__ unsigned g_flag[4 * 32 * 32];        // per-(r,c) generation flags, 128B apart

// ---------------------------------------------------------------- helpers
__device__ __forceinline__ float2 ffma2(float2 a, float2 b, float2 c) {
    unsigned long long ua = *reinterpret_cast<unsigned long long*>(&a);
    unsigned long long ub = *reinterpret_cast<unsigned long long*>(&b);
    unsigned long long uc = *reinterpret_cast<unsigned long long*>(&c);
    unsigned long long ud;
    asm("fma.rn.f32x2 %0, %1, %2, %3;" : "=l"(ud) : "l"(ua), "l"(ub), "l"(uc));
    return *reinterpret_cast<float2*>(&ud);
}
__device__ __forceinline__ float2 dup2(float s) { return make_float2(s, s); }

__device__ __forceinline__ void cp_async16(float* smem_dst, const float* gmem_src) {
    unsigned s = (unsigned)__cvta_generic_to_shared(smem_dst);
    asm volatile("cp.async.cg.shared.global [%0], [%1], 16;\n" :: "r"(s), "l"(gmem_src));
}
__device__ __forceinline__ void cp_commit() { asm volatile("cp.async.commit_group;\n"); }
template <int N> __device__ __forceinline__ void cp_wait() {
    asm volatile("cp.async.wait_group %0;\n" :: "n"(N));
}

__device__ __forceinline__ void mbar_init(uint32_t mb, uint32_t count) {
    asm volatile("mbarrier.init.shared.b64 [%0], %1;" :: "r"(mb), "r"(count) : "memory");
}
__device__ __forceinline__ void mbar_expect_tx(uint32_t mb, uint32_t bytes) {
    asm volatile("mbarrier.arrive.expect_tx.shared.b64 _, [%0], %1;" :: "r"(mb), "r"(bytes) : "memory");
}
__device__ __forceinline__ void mbar_arrive(uint32_t mb) {
    asm volatile("mbarrier.arrive.shared.b64 _, [%0];" :: "r"(mb) : "memory");
}
__device__ __forceinline__ void bulk_g2s(uint32_t dst_smem, const void* src, uint32_t bytes, uint32_t mb) {
    asm volatile("cp.async.bulk.shared::cluster.global.mbarrier::complete_tx::bytes [%0], [%1], %2, [%3];"
                 :: "r"(dst_smem), "l"(src), "r"(bytes), "r"(mb) : "memory");
}
__device__ __forceinline__ void mbar_wait(uint32_t mb, int ph) {
    asm volatile(
        "{\n\t"
        ".reg .pred P;\n\t"
        "W%=:\n\t"
        "mbarrier.try_wait.parity.acquire.cta.shared::cta.b64 P, [%0], %1, 0x989680;\n\t"
        "@P bra D%=;\n\t"
        "bra W%=;\n\t"
        "D%=:\n\t"
        "}" :: "r"(mb), "r"(ph) : "memory");
}

__device__ __forceinline__ unsigned ld_acq_gpu(const unsigned* p) {
    unsigned v;
    asm volatile("ld.acquire.gpu.global.u32 %0, [%1];" : "=r"(v) : "l"(p) : "memory");
    return v;
}
__device__ __forceinline__ void bar_named(int id, int cnt) {
    asm volatile("bar.sync %0, %1;" :: "r"(id), "r"(cnt) : "memory");
}

// ---------------------------------------------------------------- reset: zero flags (stream-ordered before rec)
__global__ void reset_kernel() {
    for (int i = threadIdx.x; i < 4 * 32 * 32; i += blockDim.x) g_flag[i] = 0u;
}

// ---------------------------------------------------------------- Kernel A: Z[t][b][h] = b[h] + sum_f x[b][f][t] * Wx[f][h]
// Tile 128t x 256h, per-thread 8x16, double-buffered cp.async.
__global__ void __launch_bounds__(256, 1) zmat_kernel(const float* __restrict__ x,
                                                      const float* __restrict__ Wx,
                                                      const float* __restrict__ bias) {
    extern __shared__ float dsm[];
    float* xs = dsm;            // [2][32][128]
    float* ws = dsm + 8192;     // [2][32][256]
    int t0 = blockIdx.x * 128;
    int h0 = blockIdx.y * 256;
    int b  = blockIdx.z;
    int tid = threadIdx.x;
    int tt = tid >> 4;          // t-group 0..15 (rows tt*8..+7)
    int tc = tid & 15;          // h-group 0..15 (cols tc*16..+15)
    const float* xb = x + (size_t)b * FF * TT;

    float2 acc[8][8];
    #pragma unroll
    for (int i = 0; i < 8; i++)
        #pragma unroll
        for (int j = 0; j < 8; j++) acc[i][j] = make_float2(0.f, 0.f);

    auto issue = [&](int ci, int buf) {
        int f0 = ci * 32;
        float* xd = xs + buf * 4096;
        float* wd = ws + buf * 8192;
        #pragma unroll
        for (int it = 0; it < 4; it++) {          // xs: 1024 float4
            int idx = it * 256 + tid;
            int f = idx >> 5, u = (idx & 31) * 4;
            cp_async16(xd + f * 128 + u, xb + (f0 + f) * TT + t0 + u);
        }
        #pragma unroll
        for (int it = 0; it < 8; it++) {          // ws: 2048 float4
            int idx = it * 256 + tid;
            int f = idx >> 6, u = (idx & 63) * 4;
            cp_async16(wd + f * 256 + u, Wx + (f0 + f) * HH + h0 + u);
        }
        cp_commit();
    };

    issue(0, 0);
    for (int ci = 0; ci < 8; ci++) {
        if (ci < 7) { issue(ci + 1, (ci + 1) & 1); cp_wait<1>(); }
        else cp_wait<0>();
        __syncthreads();
        const float* xc = xs + (ci & 1) * 4096;
        const float* wc = ws + (ci & 1) * 8192;
        #pragma unroll 8
        for (int k = 0; k < 32; k++) {
            float4 a0 = *reinterpret_cast<const float4*>(xc + k * 128 + tt * 8);
            float4 a1 = *reinterpret_cast<const float4*>(xc + k * 128 + tt * 8 + 4);
            float2 wp[8];
            #pragma unroll
            for (int q = 0; q < 4; q++) {
                float4 wq = *reinterpret_cast<const float4*>(wc + k * 256 + tc * 16 + q * 4);
                wp[q * 2]     = make_float2(wq.x, wq.y);
                wp[q * 2 + 1] = make_float2(wq.z, wq.w);
            }
            float av[8] = { a0.x, a0.y, a0.z, a0.w, a1.x, a1.y, a1.z, a1.w };
            #pragma unroll
            for (int i = 0; i < 8; i++) {
                float2 ad = dup2(av[i]);
                #pragma unroll
                for (int j = 0; j < 8; j++) acc[i][j] = ffma2(ad, wp[j], acc[i][j]);
            }
        }
        __syncthreads();
    }
    float4 bvq[4];
    #pragma unroll
    for (int q = 0; q < 4; q++) bvq[q] = *reinterpret_cast<const float4*>(bias + h0 + tc * 16 + q * 4);
    #pragma unroll
    for (int i = 0; i < 8; i++) {
        int t = t0 + tt * 8 + i;
        float* zp = g_Z + (size_t)t * (BB * HH) + b * HH + h0 + tc * 16;
        #pragma unroll
        for (int q = 0; q < 4; q++) {
            float4 o = make_float4(acc[i][q * 2].x + bvq[q].x, acc[i][q * 2].y + bvq[q].y,
                                   acc[i][q * 2 + 1].x + bvq[q].z, acc[i][q * 2 + 1].y + bvq[q].w);
            *reinterpret_cast<float4*>(zp + q * 4) = o;
        }
    }
}

// ---------------------------------------------------------------- Kernel B: persistent recurrence — warp-specialized dataflow, fp16 state
// 128 CTAs: (r in 0..3: 16 batch rows) x (c in 0..31: 32 H cols).
// 384 threads: warps 0-7 compute, warps 8-11 dedicated stagers (poll flags + 8KB TMA per chunk).
__global__ void __launch_bounds__(384, 1) rnn_rec_kernel(const float* __restrict__ Wh) {
    extern __shared__ float smem[];
    // [0..16 floats): 8 mbarriers: full[4] @ +0, consumed[4] @ +32B
    float*  wh_s = smem + 16;                                   // [k][32]  32768 floats (128KB)
    __half* st_h = reinterpret_cast<__half*>(wh_s + 32768);     // [k][16]  16384 halfs (32KB)
    float*  red_s = wh_s + 32768 + 8192;                        // [16][512] 8192 floats (32KB)
    float*  fin   = red_s + 8192;                               // [16][33]   528 floats
    uint32_t mbar0 = (uint32_t)__cvta_generic_to_shared(smem);

    int tid  = threadIdx.x;
    int wid  = tid >> 5, lane = tid & 31;
    int c = blockIdx.x & 31;                // column tile (32 cols)
    int r = blockIdx.x >> 5;                // batch row group (16 rows)
    int r16 = r * 16;

    if (tid == 0) {
        #pragma unroll
        for (int ch = 0; ch < 4; ch++) {
            mbar_init(mbar0 + ch * 8, 1);        // full: TMA expect_tx
            mbar_init(mbar0 + 32 + ch * 8, 2);   // consumed: 2 compute warps arrive
        }
    }
    for (int i = tid; i < 32768; i += 384) {
        int k = i >> 5, n = i & 31;
        wh_s[i] = Wh[k * HH + c * 32 + n];
    }
    __syncthreads();   // last block-wide sync; warps diverge below

    unsigned* myflag = &g_flag[(r * 32 + c) * 32];

    if (wid >= 8) {
        // ---------------- stager warps: one chunk each, free-running
        int ch = wid - 8;
        uint32_t fullmb = mbar0 + ch * 8;
        uint32_t consmb = mbar0 + 32 + ch * 8;
        const unsigned* pf = &g_flag[(r * 32 + ch * 8 + (lane & 7)) * 32];
        for (int t = 1; t < TT; ++t) {
            if (t >= 2) mbar_wait(consmb, t & 1);          // reads of step t-1 done
            if (lane < 8) {
                while (ld_acq_gpu(pf) < (unsigned)t) { }
            }
            __syncwarp();
            if (lane == 0) {
                asm volatile("fence.proxy.async;" ::: "memory");
                const __half* src = g_ST2h[(t + 1) & 1][r] + ch * 4096;   // 4096 halfs = 8KB
                mbar_expect_tx(fullmb, 8192u);
                uint32_t dst = (uint32_t)__cvta_generic_to_shared(st_h + ch * 4096);
                bulk_g2s(dst, src, 8192u, fullmb);
            }
        }
        return;
    }

    // ---------------- compute warps (threads 0..255)
    int s  = tid >> 4;            // k-slice 0..15, 64 k each
    int i4 = tid & 15;
    int rb = i4 >> 2;             // b-quad: rows 4*rb..4*rb+3
    int hc = i4 & 3;              // h-oct: cols 8*hc..8*hc+7
    int ch = s >> 2;              // chunk of this thread's slice (warp-uniform)
    uint32_t fullmb = mbar0 + ch * 8;
    uint32_t consmb = mbar0 + 32 + ch * 8;

    // epilogue: 2 outputs per thread
    int o  = tid * 2;
    int em = o >> 5, en = o & 31;
    int brow = r16 + em, hcol = c * 32 + en;
    int j2 = tid * 2;
    int hl = j2 >> 4, em2 = j2 & 15;

    float* zbase = g_Z + (size_t)brow * HH + hcol;

    for (int t = 0; t < TT; ++t) {
        float2 zq = *reinterpret_cast<const float2*>(zbase + (size_t)t * (BB * HH));

        float2 acc[4][4];
        #pragma unroll
        for (int bi = 0; bi < 4; bi++)
            #pragma unroll
            for (int j = 0; j < 4; j++) acc[bi][j] = make_float2(0.f, 0.f);

        if (t > 0) {
            mbar_wait(fullmb, (t - 1) & 1);
            const __half* sp = st_h + (s * 64) * 16 + rb * 4;
            const float*  wp = wh_s + (s * 64) * 32 + hc * 8;
            #pragma unroll 8
            for (int k = 0; k < 64; ++k) {
                uint2 hv = *reinterpret_cast<const uint2*>(sp); sp += 16;
                __half2 h01 = *reinterpret_cast<__half2*>(&hv.x);
                __half2 h23 = *reinterpret_cast<__half2*>(&hv.y);
                float2 f01 = __half22float2(h01);
                float2 f23 = __half22float2(h23);
                float4 wq0 = *reinterpret_cast<const float4*>(wp);
                float4 wq1 = *reinterpret_cast<const float4*>(wp + 4); wp += 32;
                float2 w0 = make_float2(wq0.x, wq0.y);
                float2 w1 = make_float2(wq0.z, wq0.w);
                float2 w2 = make_float2(wq1.x, wq1.y);
                float2 w3 = make_float2(wq1.z, wq1.w);
                float sv[4] = { f01.x, f01.y, f23.x, f23.y };
                #pragma unroll
                for (int bi = 0; bi < 4; bi++) {
                    float2 ad = dup2(sv[bi]);
                    acc[bi][0] = ffma2(ad, w0, acc[bi][0]);
                    acc[bi][1] = ffma2(ad, w1, acc[bi][1]);
                    acc[bi][2] = ffma2(ad, w2, acc[bi][2]);
                    acc[bi][3] = ffma2(ad, w3, acc[bi][3]);
                }
            }
            __syncwarp();
            if (lane == 0) mbar_arrive(consmb);   // chunk readable->overwritable by stager
        }

        // partials: [slice s][output]
        {
            float* rp = red_s + s * 512 + (rb * 4) * 32 + hc * 8;
            #pragma unroll
            for (int bi = 0; bi < 4; bi++) {
                float4 p0 = make_float4(acc[bi][0].x, acc[bi][0].y, acc[bi][1].x, acc[bi][1].y);
                float4 p1 = make_float4(acc[bi][2].x, acc[bi][2].y, acc[bi][3].x, acc[bi][3].y);
                *reinterpret_cast<float4*>(rp + bi * 32)     = p0;
                *reinterpret_cast<float4*>(rp + bi * 32 + 4) = p1;
            }
        }
        bar_named(1, 256);
        float s0, s1;
        {
            float2 v = make_float2(0.f, 0.f);
            #pragma unroll
            for (int w = 0; w < 16; w++) {
                float2 p = *reinterpret_cast<const float2*>(red_s + w * 512 + o);
                v.x += p.x; v.y += p.y;
            }
            s0 = tanhf(zq.x + v.x);
            s1 = tanhf(zq.y + v.y);
            fin[em * 33 + en]     = s0;
            fin[em * 33 + en + 1] = s1;
        }
        bar_named(1, 256);
        {
            // coalesced transposed fp16 store into the per-group slice
            float a  = fin[em2 * 33 + hl];
            float b2 = fin[(em2 + 1) * 33 + hl];
            __half2* stp = reinterpret_cast<__half2*>(g_ST2h[t & 1][r] + (size_t)(c * 32 + hl) * 16 + em2);
            *stp = __floats2half2_rn(a, b2);
        }
        bar_named(1, 256);    // all state stores ordered before release
        if (tid == 0) {
            asm volatile("fence.acq_rel.gpu;" ::: "memory");
            unsigned g = (unsigned)(t + 1);
            asm volatile("st.relaxed.gpu.global.u32 [%0], %1;" :: "l"(myflag), "r"(g) : "memory");
        }
        // g_Z store off the inter-CTA critical path (feeds kernel C only)
        *reinterpret_cast<float2*>(zbase + (size_t)t * (BB * HH)) = make_float2(s0, s1);
    }
}

// ---------------------------------------------------------------- Kernel C: out[b][t][o] = bout[o] + sum_h S[row][h] * Wout[h][o]
// Tile 128rows x 256o, per-thread 8x16, double-buffered cp.async.
__global__ void __launch_bounds__(256, 1) out_kernel(const float* __restrict__ Wout,
                                                     const float* __restrict__ bout,
                                                     float* __restrict__ out) {
    extern __shared__ float dsm[];
    float* ss = dsm;            // [2][128][32]
    float* ws = dsm + 8192;     // [2][32][256]
    int r0 = blockIdx.x * 128;
    int o0 = blockIdx.y * 256;
    int tid = threadIdx.x;
    int tr = tid >> 4;          // row-group 0..15 (rows tr*8..+7)
    int tc = tid & 15;          // o-group 0..15 (cols tc*16..+15)

    float2 acc[8][8];
    #pragma unroll
    for (int i = 0; i < 8; i++)
        #pragma unroll
        for (int j = 0; j < 8; j++) acc[i][j] = make_float2(0.f, 0.f);

    auto issue = [&](int ci, int buf) {
        int f0 = ci * 32;
        float* sd = ss + buf * 4096;
        float* wd = ws + buf * 8192;
        #pragma unroll
        for (int it = 0; it < 4; it++) {          // ss: 1024 float4 ([row][32k])
            int idx = it * 256 + tid;
            int ri = idx >> 3, kq = (idx & 7) * 4;
            cp_async16(sd + ri * 32 + kq, g_Z + (size_t)(r0 + ri) * HH + f0 + kq);
        }
        #pragma unroll
        for (int it = 0; it < 8; it++) {          // ws: 2048 float4 ([k][256])
            int idx = it * 256 + tid;
            int f = idx >> 6, u = (idx & 63) * 4;
            cp_async16(wd + f * 256 + u, Wout + (f0 + f) * OO + o0 + u);
        }
        cp_commit();
    };

    issue(0, 0);
    for (int ci = 0; ci < 32; ci++) {
        if (ci < 31) { issue(ci + 1, (ci + 1) & 1); cp_wait<1>(); }
        else cp_wait<0>();
        __syncthreads();
        const float* sc = ss + (ci & 1) * 4096;
        const float* wc = ws + (ci & 1) * 8192;
        #pragma unroll
        for (int k4 = 0; k4 < 8; k4++) {
            float4 a4[8];
            #pragma unroll
            for (int i = 0; i < 8; i++)
                a4[i] = *reinterpret_cast<const float4*>(sc + (tr * 8 + i) * 32 + k4 * 4);
            #pragma unroll
            for (int kk = 0; kk < 4; kk++) {
                int k = k4 * 4 + kk;
                float2 wp[8];
                #pragma unroll
                for (int q = 0; q < 4; q++) {
                    float4 wq = *reinterpret_cast<const float4*>(wc + k * 256 + tc * 16 + q * 4);
                    wp[q * 2]     = make_float2(wq.x, wq.y);
                    wp[q * 2 + 1] = make_float2(wq.z, wq.w);
                }
                #pragma unroll
                for (int i = 0; i < 8; i++) {
                    float av = (kk == 0) ? a4[i].x : (kk == 1) ? a4[i].y : (kk == 2) ? a4[i].z : a4[i].w;
                    float2 ad = dup2(av);
                    #pragma unroll
                    for (int j = 0; j < 8; j++) acc[i][j] = ffma2(ad, wp[j], acc[i][j]);
                }
            }
        }
        __syncthreads();
    }
    float4 bvq[4];
    #pragma unroll
    for (int q = 0; q < 4; q++) bvq[q] = *reinterpret_cast<const float4*>(bout + o0 + tc * 16 + q * 4);
    #pragma unroll
    for (int i = 0; i < 8; i++) {
        int row = r0 + tr * 8 + i;
        int t  = row >> 6;
        int bb = row & 63;
        float* op = out + (size_t)bb * (TT * OO) + t * OO + o0 + tc * 16;
        #pragma unroll
        for (int q = 0; q < 4; q++) {
            float4 o = make_float4(acc[i][q * 2].x + bvq[q].x, acc[i][q * 2].y + bvq[q].y,
                                   acc[i][q * 2 + 1].x + bvq[q].z, acc[i][q * 2 + 1].y + bvq[q].w);
            *reinterpret_cast<float4*>(op + q * 4) = o;
        }
    }
}

// ---------------------------------------------------------------- launch
extern "C" void kernel_launch(void* const* d_in, const int* in_sizes, int n_in,
                              void* d_out, int out_size) {
    const float* x    = (const float*)d_in[0];   // (B,F,T)
    const float* Wx   = (const float*)d_in[1];   // (F,H)
    const float* Wh   = (const float*)d_in[2];   // (H,H)
    const float* bv   = (const float*)d_in[3];   // (H,)
    const float* Wout = (const float*)d_in[4];   // (H,O)
    const float* bo   = (const float*)d_in[5];   // (O,)
    float* out = (float*)d_out;                  // (B,T,O)

    (void)in_sizes; (void)n_in; (void)out_size;

    // Phase 0: reset dataflow flags (stream-ordered before the recurrence)
    reset_kernel<<<1, 256>>>();

    // Phase 1: Z = x@Wx + b (128x256 tiles, 8x16/thread)
    cudaFuncSetAttribute(zmat_kernel, cudaFuncAttributeMaxDynamicSharedMemorySize, 98304);
    dim3 ga(TT / 128, HH / 256, BB);
    zmat_kernel<<<ga, 256, 98304>>>(x, Wx, bv);

    // Phase 2: persistent sequential recurrence (fp16 state, warp-specialized dataflow)
    size_t dyn = (size_t)(16 + 32768 + 8192 + 8192 + 528) * sizeof(float);  // 198784 B
    cudaFuncSetAttribute(rnn_rec_kernel, cudaFuncAttributeMaxDynamicSharedMemorySize, 232448);
    rnn_rec_kernel<<<NB, 384, dyn>>>(Wh);

    // Phase 3: output projection (128x256 tiles, 8x16/thread)
    cudaFuncSetAttribute(out_kernel, cudaFuncAttributeMaxDynamicSharedMemorySize, 98304);
    dim3 gc((TT * BB) / 128, OO / 256);
    out_kernel<<<gc, 256, 98304>>>(Wout, bo, out);
}

// round 11
// speedup vs baseline: 1.1652x; 1.1652x over previous
#include <cuda_runtime.h>
#include <cuda_bf16.h>
#include <cuda_fp16.h>
#include <math.h>
#include <stdint.h>

#define BB 64
#define FF 256
#define TT 1024
#define HH 1024
#define OO 512
#define NB 128   // persistent CTAs: 4 batch-row groups x 32 H-col tiles

// Scratch (allocation-free rule: __device__ globals)
__device__ float  g_Z[(size_t)TT * BB * HH];    // Z = x@Wx + b, later overwritten with states, [t][b][h]
__device__ __half g_ST2h[2][4][HH * 16];        // fp16 transposed state ping-pong, [buf][r-group][h][16 b]
__device__ unsigned g_flag[4 * 32 * 32];        // per-(r,c) generation flags, 128B apart

// ---------------------------------------------------------------- helpers
__device__ __forceinline__ float2 ffma2(float2 a, float2 b, float2 c) {
    unsigned long long ua = *reinterpret_cast<unsigned long long*>(&a);
    unsigned long long ub = *reinterpret_cast<unsigned long long*>(&b);
    unsigned long long uc = *reinterpret_cast<unsigned long long*>(&c);
    unsigned long long ud;
    asm("fma.rn.f32x2 %0, %1, %2, %3;" : "=l"(ud) : "l"(ua), "l"(ub), "l"(uc));
    return *reinterpret_cast<float2*>(&ud);
}
__device__ __forceinline__ float2 dup2(float s) { return make_float2(s, s); }

__device__ __forceinline__ void cp_async16(float* smem_dst, const float* gmem_src) {
    unsigned s = (unsigned)__cvta_generic_to_shared(smem_dst);
    asm volatile("cp.async.cg.shared.global [%0], [%1], 16;\n" :: "r"(s), "l"(gmem_src));
}
__device__ __forceinline__ void cp_commit() { asm volatile("cp.async.commit_group;\n"); }
template <int N> __device__ __forceinline__ void cp_wait() {
    asm volatile("cp.async.wait_group %0;\n" :: "n"(N));
}

__device__ __forceinline__ void mbar_init(uint32_t mb, uint32_t count) {
    asm volatile("mbarrier.init.shared.b64 [%0], %1;" :: "r"(mb), "r"(count) : "memory");
}
__device__ __forceinline__ void mbar_expect_tx(uint32_t mb, uint32_t bytes) {
    asm volatile("mbarrier.arrive.expect_tx.shared.b64 _, [%0], %1;" :: "r"(mb), "r"(bytes) : "memory");
}
__device__ __forceinline__ void mbar_arrive(uint32_t mb) {
    asm volatile("mbarrier.arrive.shared.b64 _, [%0];" :: "r"(mb) : "memory");
}
__device__ __forceinline__ void bulk_g2s(uint32_t dst_smem, const void* src, uint32_t bytes, uint32_t mb) {
    asm volatile("cp.async.bulk.shared::cluster.global.mbarrier::complete_tx::bytes [%0], [%1], %2, [%3];"
                 :: "r"(dst_smem), "l"(src), "r"(bytes), "r"(mb) : "memory");
}
__device__ __forceinline__ void mbar_wait(uint32_t mb, int ph) {
    asm volatile(
        "{\n\t"
        ".reg .pred P;\n\t"
        "W%=:\n\t"
        "mbarrier.try_wait.parity.acquire.cta.shared::cta.b64 P, [%0], %1, 0x989680;\n\t"
        "@P bra D%=;\n\t"
        "bra W%=;\n\t"
        "D%=:\n\t"
        "}" :: "r"(mb), "r"(ph) : "memory");
}

__device__ __forceinline__ unsigned ld_acq_gpu(const unsigned* p) {
    unsigned v;
    asm volatile("ld.acquire.gpu.global.u32 %0, [%1];" : "=r"(v) : "l"(p) : "memory");
    return v;
}
__device__ __forceinline__ void bar_named(int id, int cnt) {
    asm volatile("bar.sync %0, %1;" :: "r"(id), "r"(cnt) : "memory");
}

// ---------------------------------------------------------------- reset: zero flags (stream-ordered before rec)
__global__ void reset_kernel() {
    for (int i = threadIdx.x; i < 4 * 32 * 32; i += blockDim.x) g_flag[i] = 0u;
}

// ---------------------------------------------------------------- Kernel A: Z[t][b][h] = b[h] + sum_f x[b][f][t] * Wx[f][h]
// 128x128 tile, 8x8/thread, double-buffered, 2 CTAs/SM (R9-measured: fma~69%)
__global__ void __launch_bounds__(256, 2) zmat_kernel(const float* __restrict__ x,
                                                      const float* __restrict__ Wx,
                                                      const float* __restrict__ bias) {
    extern __shared__ float dsm[];
    float* xs = dsm;           // [2][32][128]
    float* ws = dsm + 8192;    // [2][32][128]
    int t0 = blockIdx.x * 128;
    int h0 = blockIdx.y * 128;
    int b  = blockIdx.z;
    int tid = threadIdx.x;
    int tt = tid >> 4;
    int th = tid & 15;
    const float* xb = x + (size_t)b * FF * TT;

    float2 acc[8][4];
    #pragma unroll
    for (int i = 0; i < 8; i++)
        #pragma unroll
        for (int j = 0; j < 4; j++) acc[i][j] = make_float2(0.f, 0.f);

    auto issue = [&](int ci, int buf) {
        int f0 = ci * 32;
        float* xd = xs + buf * 4096;
        float* wd = ws + buf * 4096;
        #pragma unroll
        for (int it = 0; it < 4; it++) {
            int idx = it * 256 + tid;
            int f = idx >> 5, u = (idx & 31) * 4;
            cp_async16(xd + f * 128 + u, xb + (f0 + f) * TT + t0 + u);
            cp_async16(wd + f * 128 + u, Wx + (f0 + f) * HH + h0 + u);
        }
        cp_commit();
    };

    issue(0, 0);
    for (int ci = 0; ci < 8; ci++) {
        if (ci < 7) { issue(ci + 1, (ci + 1) & 1); cp_wait<1>(); }
        else cp_wait<0>();
        __syncthreads();
        const float* xc = xs + (ci & 1) * 4096;
        const float* wc = ws + (ci & 1) * 4096;
        #pragma unroll
        for (int k = 0; k < 32; k++) {
            float4 a0 = *reinterpret_cast<const float4*>(xc + k * 128 + tt * 8);
            float4 a1 = *reinterpret_cast<const float4*>(xc + k * 128 + tt * 8 + 4);
            float4 w0 = *reinterpret_cast<const float4*>(wc + k * 128 + th * 8);
            float4 w1 = *reinterpret_cast<const float4*>(wc + k * 128 + th * 8 + 4);
            float2 wp[4] = { make_float2(w0.x, w0.y), make_float2(w0.z, w0.w),
                             make_float2(w1.x, w1.y), make_float2(w1.z, w1.w) };
            float av[8] = { a0.x, a0.y, a0.z, a0.w, a1.x, a1.y, a1.z, a1.w };
            #pragma unroll
            for (int i = 0; i < 8; i++) {
                float2 ad = dup2(av[i]);
                #pragma unroll
                for (int j = 0; j < 4; j++) acc[i][j] = ffma2(ad, wp[j], acc[i][j]);
            }
        }
        __syncthreads();
    }
    float4 bv0 = *reinterpret_cast<const float4*>(bias + h0 + th * 8);
    float4 bv1 = *reinterpret_cast<const float4*>(bias + h0 + th * 8 + 4);
    #pragma unroll
    for (int i = 0; i < 8; i++) {
        int t = t0 + tt * 8 + i;
        float* zp = g_Z + (size_t)t * (BB * HH) + b * HH + h0 + th * 8;
        float4 o0 = make_float4(acc[i][0].x + bv0.x, acc[i][0].y + bv0.y,
                                acc[i][1].x + bv0.z, acc[i][1].y + bv0.w);
        float4 o1 = make_float4(acc[i][2].x + bv1.x, acc[i][2].y + bv1.y,
                                acc[i][3].x + bv1.z, acc[i][3].y + bv1.w);
        *reinterpret_cast<float4*>(zp)     = o0;
        *reinterpret_cast<float4*>(zp + 4) = o1;
    }
}

// ---------------------------------------------------------------- Kernel B: persistent recurrence — warp-specialized dataflow, fp16 state
// 128 CTAs: (r in 0..3: 16 batch rows) x (c in 0..31: 32 H cols).
// 384 threads: warps 0-7 compute, warps 8-11 dedicated stagers (poll flags + 8KB TMA per chunk).
__global__ void __launch_bounds__(384, 1) rnn_rec_kernel(const float* __restrict__ Wh) {
    extern __shared__ float smem[];
    // [0..16 floats): 8 mbarriers: full[4] @ +0, consumed[4] @ +32B
    float*  wh_s = smem + 16;                                   // [k][32]  32768 floats (128KB)
    __half* st_h = reinterpret_cast<__half*>(wh_s + 32768);     // [k][16]  16384 halfs (32KB)
    float*  red_s = wh_s + 32768 + 8192;                        // [16][512] 8192 floats (32KB)
    float*  fin   = red_s + 8192;                               // [16][33]   528 floats
    uint32_t mbar0 = (uint32_t)__cvta_generic_to_shared(smem);

    int tid  = threadIdx.x;
    int wid  = tid >> 5, lane = tid & 31;
    int c = blockIdx.x & 31;                // column tile (32 cols)
    int r = blockIdx.x >> 5;                // batch row group (16 rows)
    int r16 = r * 16;

    if (tid == 0) {
        #pragma unroll
        for (int ch = 0; ch < 4; ch++) {
            mbar_init(mbar0 + ch * 8, 1);        // full: TMA expect_tx
            mbar_init(mbar0 + 32 + ch * 8, 2);   // consumed: 2 compute warps arrive
        }
    }
    for (int i = tid; i < 32768; i += 384) {
        int k = i >> 5, n = i & 31;
        wh_s[i] = Wh[k * HH + c * 32 + n];
    }
    __syncthreads();   // last block-wide sync; warps diverge below

    unsigned* myflag = &g_flag[(r * 32 + c) * 32];

    if (wid >= 8) {
        // ---------------- stager warps: one chunk each, free-running
        int ch = wid - 8;
        uint32_t fullmb = mbar0 + ch * 8;
        uint32_t consmb = mbar0 + 32 + ch * 8;
        const unsigned* pf = &g_flag[(r * 32 + ch * 8 + (lane & 7)) * 32];
        for (int t = 1; t < TT; ++t) {
            if (t >= 2) mbar_wait(consmb, t & 1);          // reads of step t-1 done
            if (lane < 8) {
                while (ld_acq_gpu(pf) < (unsigned)t) { }
            }
            __syncwarp();
            if (lane == 0) {
                asm volatile("fence.proxy.async;" ::: "memory");
                const __half* src = g_ST2h[(t + 1) & 1][r] + ch * 4096;   // 4096 halfs = 8KB
                mbar_expect_tx(fullmb, 8192u);
                uint32_t dst = (uint32_t)__cvta_generic_to_shared(st_h + ch * 4096);
                bulk_g2s(dst, src, 8192u, fullmb);
            }
        }
        return;
    }

    // ---------------- compute warps (threads 0..255)
    int s  = tid >> 4;            // k-slice 0..15, 64 k each
    int i4 = tid & 15;
    int rb = i4 >> 2;             // b-quad: rows 4*rb..4*rb+3
    int hc = i4 & 3;              // h-oct: cols 8*hc..8*hc+7
    int ch = s >> 2;              // chunk of this thread's slice (warp-uniform)
    uint32_t fullmb = mbar0 + ch * 8;
    uint32_t consmb = mbar0 + 32 + ch * 8;

    // epilogue: 2 outputs per thread
    int o  = tid * 2;
    int em = o >> 5, en = o & 31;
    int brow = r16 + em, hcol = c * 32 + en;
    int j2 = tid * 2;
    int hl = j2 >> 4, em2 = j2 & 15;

    float* zbase = g_Z + (size_t)brow * HH + hcol;

    for (int t = 0; t < TT; ++t) {
        float2 zq = *reinterpret_cast<const float2*>(zbase + (size_t)t * (BB * HH));

        float2 acc[4][4];
        #pragma unroll
        for (int bi = 0; bi < 4; bi++)
            #pragma unroll
            for (int j = 0; j < 4; j++) acc[bi][j] = make_float2(0.f, 0.f);

        if (t > 0) {
            mbar_wait(fullmb, (t - 1) & 1);
            const __half* sp = st_h + (s * 64) * 16 + rb * 4;
            const float*  wp = wh_s + (s * 64) * 32 + hc * 8;
            #pragma unroll 8
            for (int k = 0; k < 64; ++k) {
                uint2 hv = *reinterpret_cast<const uint2*>(sp); sp += 16;
                __half2 h01 = *reinterpret_cast<__half2*>(&hv.x);
                __half2 h23 = *reinterpret_cast<__half2*>(&hv.y);
                float2 f01 = __half22float2(h01);
                float2 f23 = __half22float2(h23);
                float4 wq0 = *reinterpret_cast<const float4*>(wp);
                float4 wq1 = *reinterpret_cast<const float4*>(wp + 4); wp += 32;
                float2 w0 = make_float2(wq0.x, wq0.y);
                float2 w1 = make_float2(wq0.z, wq0.w);
                float2 w2 = make_float2(wq1.x, wq1.y);
                float2 w3 = make_float2(wq1.z, wq1.w);
                float sv[4] = { f01.x, f01.y, f23.x, f23.y };
                #pragma unroll
                for (int bi = 0; bi < 4; bi++) {
                    float2 ad = dup2(sv[bi]);
                    acc[bi][0] = ffma2(ad, w0, acc[bi][0]);
                    acc[bi][1] = ffma2(ad, w1, acc[bi][1]);
                    acc[bi][2] = ffma2(ad, w2, acc[bi][2]);
                    acc[bi][3] = ffma2(ad, w3, acc[bi][3]);
                }
            }
            __syncwarp();
            if (lane == 0) mbar_arrive(consmb);   // chunk readable->overwritable by stager
        }

        // partials: [slice s][output]
        {
            float* rp = red_s + s * 512 + (rb * 4) * 32 + hc * 8;
            #pragma unroll
            for (int bi = 0; bi < 4; bi++) {
                float4 p0 = make_float4(acc[bi][0].x, acc[bi][0].y, acc[bi][1].x, acc[bi][1].y);
                float4 p1 = make_float4(acc[bi][2].x, acc[bi][2].y, acc[bi][3].x, acc[bi][3].y);
                *reinterpret_cast<float4*>(rp + bi * 32)     = p0;
                *reinterpret_cast<float4*>(rp + bi * 32 + 4) = p1;
            }
        }
        bar_named(1, 256);
        float s0, s1;
        {
            float2 v = make_float2(0.f, 0.f);
            #pragma unroll
            for (int w = 0; w < 16; w++) {
                float2 p = *reinterpret_cast<const float2*>(red_s + w * 512 + o);
                v.x += p.x; v.y += p.y;
            }
            s0 = tanhf(zq.x + v.x);
            s1 = tanhf(zq.y + v.y);
            fin[em * 33 + en]     = s0;
            fin[em * 33 + en + 1] = s1;
        }
        bar_named(1, 256);
        {
            // coalesced transposed fp16 store into the per-group slice
            float a  = fin[em2 * 33 + hl];
            float b2 = fin[(em2 + 1) * 33 + hl];
            __half2* stp = reinterpret_cast<__half2*>(g_ST2h[t & 1][r] + (size_t)(c * 32 + hl) * 16 + em2);
            *stp = __floats2half2_rn(a, b2);
        }
        bar_named(1, 256);    // all state stores ordered before release
        if (tid == 0) {
            asm volatile("fence.acq_rel.gpu;" ::: "memory");
            unsigned g = (unsigned)(t + 1);
            asm volatile("st.relaxed.gpu.global.u32 [%0], %1;" :: "l"(myflag), "r"(g) : "memory");
        }
        // g_Z store off the inter-CTA critical path (feeds kernel C only)
        *reinterpret_cast<float2*>(zbase + (size_t)t * (BB * HH)) = make_float2(s0, s1);
    }
}

// ---------------------------------------------------------------- Kernel C: out[b][t][o] = bout[o] + sum_h S[row][h] * Wout[h][o]
// 128x128 tile, 8x8/thread, double-buffered, 2 CTAs/SM (R9-measured: fma~69%)
__global__ void __launch_bounds__(256, 2) out_kernel(const float* __restrict__ Wout,
                                                     const float* __restrict__ bout,
                                                     float* __restrict__ out) {
    extern __shared__ float dsm[];
    float* ss = dsm;           // [2][128][32]
    float* ws = dsm + 8192;    // [2][32][128]
    int r0 = blockIdx.x * 128;
    int o0 = blockIdx.y * 128;
    int tid = threadIdx.x;
    int tt = tid >> 4, th = tid & 15;

    float2 acc[8][4];
    #pragma unroll
    for (int i = 0; i < 8; i++)
        #pragma unroll
        for (int j = 0; j < 4; j++) acc[i][j] = make_float2(0.f, 0.f);

    auto issue = [&](int ci, int buf) {
        int f0 = ci * 32;
        float* sd = ss + buf * 4096;
        float* wd = ws + buf * 4096;
        #pragma unroll
        for (int it = 0; it < 4; it++) {
            int idx = it * 256 + tid;
            int ri = idx >> 3, kq = (idx & 7) * 4;
            cp_async16(sd + ri * 32 + kq, g_Z + (size_t)(r0 + ri) * HH + f0 + kq);
            int f = idx >> 5, u = (idx & 31) * 4;
            cp_async16(wd + f * 128 + u, Wout + (f0 + f) * OO + o0 + u);
        }
        cp_commit();
    };

    issue(0, 0);
    for (int ci = 0; ci < 32; ci++) {
        if (ci < 31) { issue(ci + 1, (ci + 1) & 1); cp_wait<1>(); }
        else cp_wait<0>();
        __syncthreads();
        const float* sc = ss + (ci & 1) * 4096;
        const float* wc = ws + (ci & 1) * 4096;
        #pragma unroll
        for (int k = 0; k < 32; k++) {
            float av[8];
            #pragma unroll
            for (int i = 0; i < 8; i++) av[i] = sc[(tt * 8 + i) * 32 + k];
            float4 w0 = *reinterpret_cast<const float4*>(wc + k * 128 + th * 8);
            float4 w1 = *reinterpret_cast<const float4*>(wc + k * 128 + th * 8 + 4);
            float2 wp[4] = { make_float2(w0.x, w0.y), make_float2(w0.z, w0.w),
                             make_float2(w1.x, w1.y), make_float2(w1.z, w1.w) };
            #pragma unroll
            for (int i = 0; i < 8; i++) {
                float2 ad = dup2(av[i]);
                #pragma unroll
                for (int j = 0; j < 4; j++) acc[i][j] = ffma2(ad, wp[j], acc[i][j]);
            }
        }
        __syncthreads();
    }
    float4 bv0 = *reinterpret_cast<const float4*>(bout + o0 + th * 8);
    float4 bv1 = *reinterpret_cast<const float4*>(bout + o0 + th * 8 + 4);
    #pragma unroll
    for (int i = 0; i < 8; i++) {
        int row = r0 + tt * 8 + i;
        int t  = row >> 6;
        int bb = row & 63;
        float* op = out + (size_t)bb * (TT * OO) + t * OO + o0 + th * 8;
        float4 q0 = make_float4(acc[i][0].x + bv0.x, acc[i][0].y + bv0.y,
                                acc[i][1].x + bv0.z, acc[i][1].y + bv0.w);
        float4 q1 = make_float4(acc[i][2].x + bv1.x, acc[i][2].y + bv1.y,
                                acc[i][3].x + bv1.z, acc[i][3].y + bv1.w);
        *reinterpret_cast<float4*>(op)     = q0;
        *reinterpret_cast<float4*>(op + 4) = q1;
    }
}

// ---------------------------------------------------------------- launch
extern "C" void kernel_launch(void* const* d_in, const int* in_sizes, int n_in,
                              void* d_out, int out_size) {
    const float* x    = (const float*)d_in[0];   // (B,F,T)
    const float* Wx   = (const float*)d_in[1];   // (F,H)
    const float* Wh   = (const float*)d_in[2];   // (H,H)
    const float* bv   = (const float*)d_in[3];   // (H,)
    const float* Wout = (const float*)d_in[4];   // (H,O)
    const float* bo   = (const float*)d_in[5];   // (O,)
    float* out = (float*)d_out;                  // (B,T,O)

    (void)in_sizes; (void)n_in; (void)out_size;

    // Phase 0: reset dataflow flags (stream-ordered before the recurrence)
    reset_kernel<<<1, 256>>>();

    // Phase 1: Z = x@Wx + b (128x128 tiles, 8x8/thread, 2 CTAs/SM)
    cudaFuncSetAttribute(zmat_kernel, cudaFuncAttributeMaxDynamicSharedMemorySize, 65536);
    dim3 ga(TT / 128, HH / 128, BB);
    zmat_kernel<<<ga, 256, 65536>>>(x, Wx, bv);

    // Phase 2: persistent sequential recurrence (fp16 state, warp-specialized dataflow)
    size_t dyn = (size_t)(16 + 32768 + 8192 + 8192 + 528) * sizeof(float);  // 198784 B
    cudaFuncSetAttribute(rnn_rec_kernel, cudaFuncAttributeMaxDynamicSharedMemorySize, 232448);
    rnn_rec_kernel<<<NB, 384, dyn>>>(Wh);

    // Phase 3: output projection (128x128 tiles, 8x8/thread, 2 CTAs/SM)
    cudaFuncSetAttribute(out_kernel, cudaFuncAttributeMaxDynamicSharedMemorySize, 65536);
    dim3 gc((TT * BB) / 128, OO / 128);
    out_kernel<<<gc, 256, 65536>>>(Wout, bo, out);
}

// round 12
// speedup vs baseline: 1.8499x; 1.5877x over previous
#include <cuda_runtime.h>
#include <cuda_bf16.h>
#include <cuda_fp16.h>
#include <math.h>
#include <stdint.h>

#define BB 64
#define FF 256
#define TT 1024
#define HH 1024
#define OO 512
#define NB 128   // persistent CTAs: 4 batch-row groups x 32 H-col tiles

// Scratch (allocation-free rule: __device__ globals)
__device__ float  g_Z[(size_t)TT * BB * HH];    // Z = x@Wx + b, later overwritten with states, [t][b][h]
__device__ __half g_ST2h[2][4][HH * 16];        // fp16 transposed state ping-pong, [buf][r-group][h][16 b]
__device__ unsigned g_flag[4 * 32 * 32];        // per-(r,c) generation flags, 128B apart

// ---------------------------------------------------------------- helpers
__device__ __forceinline__ float2 ffma2(float2 a, float2 b, float2 c) {
    unsigned long long ua = *reinterpret_cast<unsigned long long*>(&a);
    unsigned long long ub = *reinterpret_cast<unsigned long long*>(&b);
    unsigned long long uc = *reinterpret_cast<unsigned long long*>(&c);
    unsigned long long ud;
    asm("fma.rn.f32x2 %0, %1, %2, %3;" : "=l"(ud) : "l"(ua), "l"(ub), "l"(uc));
    return *reinterpret_cast<float2*>(&ud);
}
__device__ __forceinline__ float2 dup2(float s) { return make_float2(s, s); }

__device__ __forceinline__ void cp_async16(float* smem_dst, const float* gmem_src) {
    unsigned s = (unsigned)__cvta_generic_to_shared(smem_dst);
    asm volatile("cp.async.cg.shared.global [%0], [%1], 16;\n" :: "r"(s), "l"(gmem_src));
}
__device__ __forceinline__ void cp_commit() { asm volatile("cp.async.commit_group;\n"); }
template <int N> __device__ __forceinline__ void cp_wait() {
    asm volatile("cp.async.wait_group %0;\n" :: "n"(N));
}

__device__ __forceinline__ void mbar_init(uint32_t mb, uint32_t count) {
    asm volatile("mbarrier.init.shared.b64 [%0], %1;" :: "r"(mb), "r"(count) : "memory");
}
__device__ __forceinline__ void mbar_expect_tx(uint32_t mb, uint32_t bytes) {
    asm volatile("mbarrier.arrive.expect_tx.shared.b64 _, [%0], %1;" :: "r"(mb), "r"(bytes) : "memory");
}
__device__ __forceinline__ void mbar_arrive(uint32_t mb) {
    asm volatile("mbarrier.arrive.shared.b64 _, [%0];" :: "r"(mb) : "memory");
}
__device__ __forceinline__ void bulk_g2s(uint32_t dst_smem, const void* src, uint32_t bytes, uint32_t mb) {
    asm volatile("cp.async.bulk.shared::cluster.global.mbarrier::complete_tx::bytes [%0], [%1], %2, [%3];"
                 :: "r"(dst_smem), "l"(src), "r"(bytes), "r"(mb) : "memory");
}
__device__ __forceinline__ void mbar_wait(uint32_t mb, int ph) {
    asm volatile(
        "{\n\t"
        ".reg .pred P;\n\t"
        "W%=:\n\t"
        "mbarrier.try_wait.parity.acquire.cta.shared::cta.b64 P, [%0], %1, 0x989680;\n\t"
        "@P bra D%=;\n\t"
        "bra W%=;\n\t"
        "D%=:\n\t"
        "}" :: "r"(mb), "r"(ph) : "memory");
}

__device__ __forceinline__ unsigned ld_acq_gpu(const unsigned* p) {
    unsigned v;
    asm volatile("ld.acquire.gpu.global.u32 %0, [%1];" : "=r"(v) : "l"(p) : "memory");
    return v;
}
__device__ __forceinline__ void bar_named(int id, int cnt) {
    asm volatile("bar.sync %0, %1;" :: "r"(id), "r"(cnt) : "memory");
}

__device__ __forceinline__ void ldsm_x4_trans(uint32_t& r0, uint32_t& r1, uint32_t& r2, uint32_t& r3, uint32_t addr) {
    asm volatile("ldmatrix.sync.aligned.m8n8.x4.trans.shared.b16 {%0,%1,%2,%3}, [%4];"
                 : "=r"(r0), "=r"(r1), "=r"(r2), "=r"(r3) : "r"(addr));
}
__device__ __forceinline__ void ldsm_x2_trans(uint32_t& r0, uint32_t& r1, uint32_t addr) {
    asm volatile("ldmatrix.sync.aligned.m8n8.x2.trans.shared.b16 {%0,%1}, [%2];"
                 : "=r"(r0), "=r"(r1) : "r"(addr));
}
__device__ __forceinline__ void mma16816(float& d0, float& d1, float& d2, float& d3,
                                         uint32_t a0, uint32_t a1, uint32_t a2, uint32_t a3,
                                         uint32_t b0, uint32_t b1) {
    asm volatile("mma.sync.aligned.m16n8k16.row.col.f32.f16.f16.f32 "
                 "{%0,%1,%2,%3}, {%4,%5,%6,%7}, {%8,%9}, {%0,%1,%2,%3};"
                 : "+f"(d0), "+f"(d1), "+f"(d2), "+f"(d3)
                 : "r"(a0), "r"(a1), "r"(a2), "r"(a3), "r"(b0), "r"(b1));
}

// ---------------------------------------------------------------- reset: zero flags (stream-ordered before rec)
__global__ void reset_kernel() {
    for (int i = threadIdx.x; i < 4 * 32 * 32; i += blockDim.x) g_flag[i] = 0u;
}

// ---------------------------------------------------------------- Kernel A: Z[t][b][h] = b[h] + sum_f x[b][f][t] * Wx[f][h]
__global__ void __launch_bounds__(256, 2) zmat_kernel(const float* __restrict__ x,
                                                      const float* __restrict__ Wx,
                                                      const float* __restrict__ bias) {
    extern __shared__ float dsm[];
    float* xs = dsm;           // [2][32][128]
    float* ws = dsm + 8192;    // [2][32][128]
    int t0 = blockIdx.x * 128;
    int h0 = blockIdx.y * 128;
    int b  = blockIdx.z;
    int tid = threadIdx.x;
    int tt = tid >> 4;
    int th = tid & 15;
    const float* xb = x + (size_t)b * FF * TT;

    float2 acc[8][4];
    #pragma unroll
    for (int i = 0; i < 8; i++)
        #pragma unroll
        for (int j = 0; j < 4; j++) acc[i][j] = make_float2(0.f, 0.f);

    auto issue = [&](int ci, int buf) {
        int f0 = ci * 32;
        float* xd = xs + buf * 4096;
        float* wd = ws + buf * 4096;
        #pragma unroll
        for (int it = 0; it < 4; it++) {
            int idx = it * 256 + tid;
            int f = idx >> 5, u = (idx & 31) * 4;
            cp_async16(xd + f * 128 + u, xb + (f0 + f) * TT + t0 + u);
            cp_async16(wd + f * 128 + u, Wx + (f0 + f) * HH + h0 + u);
        }
        cp_commit();
    };

    issue(0, 0);
    for (int ci = 0; ci < 8; ci++) {
        if (ci < 7) { issue(ci + 1, (ci + 1) & 1); cp_wait<1>(); }
        else cp_wait<0>();
        __syncthreads();
        const float* xc = xs + (ci & 1) * 4096;
        const float* wc = ws + (ci & 1) * 4096;
        #pragma unroll
        for (int k = 0; k < 32; k++) {
            float4 a0 = *reinterpret_cast<const float4*>(xc + k * 128 + tt * 8);
            float4 a1 = *reinterpret_cast<const float4*>(xc + k * 128 + tt * 8 + 4);
            float4 w0 = *reinterpret_cast<const float4*>(wc + k * 128 + th * 8);
            float4 w1 = *reinterpret_cast<const float4*>(wc + k * 128 + th * 8 + 4);
            float2 wp[4] = { make_float2(w0.x, w0.y), make_float2(w0.z, w0.w),
                             make_float2(w1.x, w1.y), make_float2(w1.z, w1.w) };
            float av[8] = { a0.x, a0.y, a0.z, a0.w, a1.x, a1.y, a1.z, a1.w };
            #pragma unroll
            for (int i = 0; i < 8; i++) {
                float2 ad = dup2(av[i]);
                #pragma unroll
                for (int j = 0; j < 4; j++) acc[i][j] = ffma2(ad, wp[j], acc[i][j]);
            }
        }
        __syncthreads();
    }
    float4 bv0 = *reinterpret_cast<const float4*>(bias + h0 + th * 8);
    float4 bv1 = *reinterpret_cast<const float4*>(bias + h0 + th * 8 + 4);
    #pragma unroll
    for (int i = 0; i < 8; i++) {
        int t = t0 + tt * 8 + i;
        float* zp = g_Z + (size_t)t * (BB * HH) + b * HH + h0 + th * 8;
        float4 o0 = make_float4(acc[i][0].x + bv0.x, acc[i][0].y + bv0.y,
                                acc[i][1].x + bv0.z, acc[i][1].y + bv0.w);
        float4 o1 = make_float4(acc[i][2].x + bv1.x, acc[i][2].y + bv1.y,
                                acc[i][3].x + bv1.z, acc[i][3].y + bv1.w);
        *reinterpret_cast<float4*>(zp)     = o0;
        *reinterpret_cast<float4*>(zp + 4) = o1;
    }
}

// ---------------------------------------------------------------- Kernel B: persistent recurrence — HMMA (mma.sync fp16) + dataflow
// 128 CTAs: (r: 16 batch rows) x (c: 32 H cols). 384 threads: warps 0-7 compute (K-split
// 128 k each), warps 8-11 stagers. Wh fp16 B-fragments preloaded into REGISTERS once.
// Per step per warp: 8 ldmatrix.x4.trans (A from staged [k][16b] fp16 state) + 32 HMMA.
__global__ void __launch_bounds__(384, 1) rnn_rec_kernel(const float* __restrict__ Wh) {
    extern __shared__ float smem[];
    // [0..16 floats): 8 mbarriers: full[4] @ +0, consumed[4] @ +32B
    __half* wh_h = reinterpret_cast<__half*>(smem + 16);        // [1024][32] halfs (64KB), init-only
    __half* st_h = reinterpret_cast<__half*>(smem + 16 + 16384);// [1024][16] halfs (32KB)
    float*  red_s = smem + 16 + 16384 + 8192;                   // [8][512] floats (16KB)
    float*  fin   = red_s + 4096;                               // [16][33] floats
    uint32_t mbar0 = (uint32_t)__cvta_generic_to_shared(smem);
    uint32_t st_base = (uint32_t)__cvta_generic_to_shared(st_h);
    uint32_t wh_base = (uint32_t)__cvta_generic_to_shared(wh_h);

    int tid  = threadIdx.x;
    int wid  = tid >> 5, lane = tid & 31;
    int c = blockIdx.x & 31;                // column tile (32 cols)
    int r = blockIdx.x >> 5;                // batch row group (16 rows)
    int r16 = r * 16;

    if (tid == 0) {
        #pragma unroll
        for (int ch = 0; ch < 4; ch++) {
            mbar_init(mbar0 + ch * 8, 1);        // full: TMA expect_tx
            mbar_init(mbar0 + 32 + ch * 8, 2);   // consumed: 2 compute warps arrive
        }
    }
    // Wh tile -> fp16 SMEM [k][32]
    for (int i = tid; i < 32768; i += 384) {
        int k = i >> 5, n = i & 31;
        wh_h[i] = __float2half_rn(Wh[k * HH + c * 32 + n]);
    }
    __syncthreads();   // last block-wide sync; warps diverge below

    unsigned* myflag = &g_flag[(r * 32 + c) * 32];

    if (wid >= 8) {
        // ---------------- stager warps: one chunk each, free-running
        int ch = wid - 8;
        uint32_t fullmb = mbar0 + ch * 8;
        uint32_t consmb = mbar0 + 32 + ch * 8;
        const unsigned* pf = &g_flag[(r * 32 + ch * 8 + (lane & 7)) * 32];
        for (int t = 1; t < TT; ++t) {
            if (t >= 2) mbar_wait(consmb, t & 1);          // reads of step t-1 done
            if (lane < 8) {
                while (ld_acq_gpu(pf) < (unsigned)t) { }
            }
            __syncwarp();
            if (lane == 0) {
                asm volatile("fence.proxy.async;" ::: "memory");
                const __half* src = g_ST2h[(t + 1) & 1][r] + ch * 4096;   // 4096 halfs = 8KB
                mbar_expect_tx(fullmb, 8192u);
                uint32_t dst = (uint32_t)__cvta_generic_to_shared(st_h + ch * 4096);
                bulk_g2s(dst, src, 8192u, fullmb);
            }
        }
        return;
    }

    // ---------------- compute warps (threads 0..255), warp w owns k in [w*128, (w+1)*128)
    int w = wid;
    int ch = w >> 1;                       // chunk (256 k) this warp's slice lives in
    uint32_t fullmb = mbar0 + ch * 8;
    uint32_t consmb = mbar0 + 32 + ch * 8;

    // Preload B fragments (Wh^T tiles) into registers: 8 k-tiles x 4 n-tiles x 2 regs.
    // b0 tile = (k0-7, n0-7): lanes 0-7 -> wh rows k..k+7; b1: lanes 8-15 -> rows k+8..k+15.
    uint32_t Bf[8][4][2];
    {
        int brow = ((lane >> 3) & 1) * 8 + (lane & 7);
        #pragma unroll
        for (int kt = 0; kt < 8; kt++) {
            int krow = w * 128 + kt * 16 + brow;
            #pragma unroll
            for (int nt = 0; nt < 4; nt++) {
                uint32_t addr = wh_base + (uint32_t)(krow * 32 + nt * 8) * 2;
                ldsm_x2_trans(Bf[kt][nt][0], Bf[kt][nt][1], addr);
            }
        }
    }

    // A ldmatrix address pattern (x4.trans from [k][16b]):
    // group g=lane/8: g0->a0(k0-7,b0-7) g1->a1(k0-7,b8-15) g2->a2(k8-15,b0-7) g3->a3(k8-15,b8-15)
    int arow = ((lane >> 4) & 1) * 8 + (lane & 7);   // +8 rows for groups 2,3
    int acol = ((lane >> 3) & 1) * 8;                // +8 cols for groups 1,3

    // epilogue mapping: 2 outputs per thread
    int o  = tid * 2;
    int em = o >> 5, en = o & 31;
    int brow2 = r16 + em, hcol = c * 32 + en;
    int j2 = tid * 2;
    int hl = j2 >> 4, em2 = j2 & 15;

    // D-frag store mapping
    int m0 = lane >> 2;
    int nc = (lane & 3) * 2;

    float* zbase = g_Z + (size_t)brow2 * HH + hcol;

    for (int t = 0; t < TT; ++t) {
        float2 zq = *reinterpret_cast<const float2*>(zbase + (size_t)t * (BB * HH));

        float d[4][4];
        #pragma unroll
        for (int nt = 0; nt < 4; nt++)
            #pragma unroll
            for (int j = 0; j < 4; j++) d[nt][j] = 0.f;

        if (t > 0) {
            mbar_wait(fullmb, (t - 1) & 1);
            #pragma unroll
            for (int kt = 0; kt < 8; kt++) {
                uint32_t a0, a1, a2, a3;
                uint32_t addr = st_base + (uint32_t)((w * 128 + kt * 16 + arow) * 16 + acol) * 2;
                ldsm_x4_trans(a0, a1, a2, a3, addr);
                #pragma unroll
                for (int nt = 0; nt < 4; nt++)
                    mma16816(d[nt][0], d[nt][1], d[nt][2], d[nt][3],
                             a0, a1, a2, a3, Bf[kt][nt][0], Bf[kt][nt][1]);
            }
            __syncwarp();
            if (lane == 0) mbar_arrive(consmb);   // chunk readable -> overwritable by stager
        }

        // partials: red_s[w][m*32 + n]
        {
            float* rp = red_s + w * 512;
            #pragma unroll
            for (int nt = 0; nt < 4; nt++) {
                *reinterpret_cast<float2*>(rp + m0 * 32 + nt * 8 + nc)       = make_float2(d[nt][0], d[nt][1]);
                *reinterpret_cast<float2*>(rp + (m0 + 8) * 32 + nt * 8 + nc) = make_float2(d[nt][2], d[nt][3]);
            }
        }
        bar_named(1, 256);
        float s0, s1;
        {
            float2 v = make_float2(0.f, 0.f);
            #pragma unroll
            for (int ww = 0; ww < 8; ww++) {
                float2 p = *reinterpret_cast<const float2*>(red_s + ww * 512 + o);
                v.x += p.x; v.y += p.y;
            }
            s0 = tanhf(zq.x + v.x);
            s1 = tanhf(zq.y + v.y);
            fin[em * 33 + en]     = s0;
            fin[em * 33 + en + 1] = s1;
        }
        bar_named(1, 256);
        {
            // coalesced transposed fp16 state store
            float a  = fin[em2 * 33 + hl];
            float b2 = fin[(em2 + 1) * 33 + hl];
            __half2* stp = reinterpret_cast<__half2*>(g_ST2h[t & 1][r] + (size_t)(c * 32 + hl) * 16 + em2);
            *stp = __floats2half2_rn(a, b2);
        }
        bar_named(1, 256);    // all state stores ordered before release
        if (tid == 0) {
            asm volatile("fence.acq_rel.gpu;" ::: "memory");
            unsigned g = (unsigned)(t + 1);
            asm volatile("st.relaxed.gpu.global.u32 [%0], %1;" :: "l"(myflag), "r"(g) : "memory");
        }
        // g_Z store off the inter-CTA critical path (feeds kernel C only)
        *reinterpret_cast<float2*>(zbase + (size_t)t * (BB * HH)) = make_float2(s0, s1);
    }
}

// ---------------------------------------------------------------- Kernel C: out[b][t][o] = bout[o] + sum_h S[row][h] * Wout[h][o]
__global__ void __launch_bounds__(256, 2) out_kernel(const float* __restrict__ Wout,
                                                     const float* __restrict__ bout,
                                                     float* __restrict__ out) {
    extern __shared__ float dsm[];
    float* ss = dsm;           // [2][128][32]
    float* ws = dsm + 8192;    // [2][32][128]
    int r0 = blockIdx.x * 128;
    int o0 = blockIdx.y * 128;
    int tid = threadIdx.x;
    int tt = tid >> 4, th = tid & 15;

    float2 acc[8][4];
    #pragma unroll
    for (int i = 0; i < 8; i++)
        #pragma unroll
        for (int j = 0; j < 4; j++) acc[i][j] = make_float2(0.f, 0.f);

    auto issue = [&](int ci, int buf) {
        int f0 = ci * 32;
        float* sd = ss + buf * 4096;
        float* wd = ws + buf * 4096;
        #pragma unroll
        for (int it = 0; it < 4; it++) {
            int idx = it * 256 + tid;
            int ri = idx >> 3, kq = (idx & 7) * 4;
            cp_async16(sd + ri * 32 + kq, g_Z + (size_t)(r0 + ri) * HH + f0 + kq);
            int f = idx >> 5, u = (idx & 31) * 4;
            cp_async16(wd + f * 128 + u, Wout + (f0 + f) * OO + o0 + u);
        }
        cp_commit();
    };

    issue(0, 0);
    for (int ci = 0; ci < 32; ci++) {
        if (ci < 31) { issue(ci + 1, (ci + 1) & 1); cp_wait<1>(); }
        else cp_wait<0>();
        __syncthreads();
        const float* sc = ss + (ci & 1) * 4096;
        const float* wc = ws + (ci & 1) * 4096;
        #pragma unroll
        for (int k = 0; k < 32; k++) {
            float av[8];
            #pragma unroll
            for (int i = 0; i < 8; i++) av[i] = sc[(tt * 8 + i) * 32 + k];
            float4 w0 = *reinterpret_cast<const float4*>(wc + k * 128 + th * 8);
            float4 w1 = *reinterpret_cast<const float4*>(wc + k * 128 + th * 8 + 4);
            float2 wp[4] = { make_float2(w0.x, w0.y), make_float2(w0.z, w0.w),
                             make_float2(w1.x, w1.y), make_float2(w1.z, w1.w) };
            #pragma unroll
            for (int i = 0; i < 8; i++) {
                float2 ad = dup2(av[i]);
                #pragma unroll
                for (int j = 0; j < 4; j++) acc[i][j] = ffma2(ad, wp[j], acc[i][j]);
            }
        }
        __syncthreads();
    }
    float4 bv0 = *reinterpret_cast<const float4*>(bout + o0 + th * 8);
    float4 bv1 = *reinterpret_cast<const float4*>(bout + o0 + th * 8 + 4);
    #pragma unroll
    for (int i = 0; i < 8; i++) {
        int row = r0 + tt * 8 + i;
        int t  = row >> 6;
        int bb = row & 63;
        float* op = out + (size_t)bb * (TT * OO) + t * OO + o0 + th * 8;
        float4 q0 = make_float4(acc[i][0].x + bv0.x, acc[i][0].y + bv0.y,
                                acc[i][1].x + bv0.z, acc[i][1].y + bv0.w);
        float4 q1 = make_float4(acc[i][2].x + bv1.x, acc[i][2].y + bv1.y,
                                acc[i][3].x + bv1.z, acc[i][3].y + bv1.w);
        *reinterpret_cast<float4*>(op)     = q0;
        *reinterpret_cast<float4*>(op + 4) = q1;
    }
}

// ---------------------------------------------------------------- launch
extern "C" void kernel_launch(void* const* d_in, const int* in_sizes, int n_in,
                              void* d_out, int out_size) {
    const float* x    = (const float*)d_in[0];   // (B,F,T)
    const float* Wx   = (const float*)d_in[1];   // (F,H)
    const float* Wh   = (const float*)d_in[2];   // (H,H)
    const float* bv   = (const float*)d_in[3];   // (H,)
    const float* Wout = (const float*)d_in[4];   // (H,O)
    const float* bo   = (const float*)d_in[5];   // (O,)
    float* out = (float*)d_out;                  // (B,T,O)

    (void)in_sizes; (void)n_in; (void)out_size;

    // Phase 0: reset dataflow flags (stream-ordered before the recurrence)
    reset_kernel<<<1, 256>>>();

    // Phase 1: Z = x@Wx + b (128x128 tiles, 8x8/thread, 2 CTAs/SM)
    cudaFuncSetAttribute(zmat_kernel, cudaFuncAttributeMaxDynamicSharedMemorySize, 65536);
    dim3 ga(TT / 128, HH / 128, BB);
    zmat_kernel<<<ga, 256, 65536>>>(x, Wx, bv);

    // Phase 2: persistent recurrence (HMMA fp16, warp-specialized dataflow)
    size_t dyn = (size_t)(16 + 16384 + 8192 + 4096 + 528) * sizeof(float);  // 116864 B
    cudaFuncSetAttribute(rnn_rec_kernel, cudaFuncAttributeMaxDynamicSharedMemorySize, 232448);
    rnn_rec_kernel<<<NB, 384, dyn>>>(Wh);

    // Phase 3: output projection (128x128 tiles, 8x8/thread, 2 CTAs/SM)
    cudaFuncSetAttribute(out_kernel, cudaFuncAttributeMaxDynamicSharedMemorySize, 65536);
    dim3 gc((TT * BB) / 128, OO / 128);
    out_kernel<<<gc, 256, 65536>>>(Wout, bo, out);
}

// round 13
// speedup vs baseline: 2.3112x; 1.2493x over previous
#include <cuda_runtime.h>
#include <cuda_bf16.h>
#include <cuda_fp16.h>
#include <math.h>
#include <stdint.h>

#define BB 64
#define FF 256
#define TT 1024
#define HH 1024
#define OO 512
#define NB 128   // persistent CTAs: 4 batch-row groups x 32 H-col tiles

// Scratch (allocation-free rule: __device__ globals)
__device__ float  g_Z[(size_t)TT * BB * HH];    // Z = x@Wx + b, [t][b][h] (fp32, read by rec)
__device__ __half g_Sh[(size_t)TT * BB * HH];   // fp16 states row-major [t*64+b][h] (feeds out_kernel)
__device__ __half g_ST2h[2][4][HH * 16];        // fp16 transposed state ping-pong, [buf][r-group][h][16 b]
__device__ __half g_Wouth[HH * OO];             // fp16 Wout
__device__ unsigned g_flag[4 * 32 * 32];        // per-(r,c) generation flags, 128B apart

// ---------------------------------------------------------------- helpers
__device__ __forceinline__ float2 ffma2(float2 a, float2 b, float2 c) {
    unsigned long long ua = *reinterpret_cast<unsigned long long*>(&a);
    unsigned long long ub = *reinterpret_cast<unsigned long long*>(&b);
    unsigned long long uc = *reinterpret_cast<unsigned long long*>(&c);
    unsigned long long ud;
    asm("fma.rn.f32x2 %0, %1, %2, %3;" : "=l"(ud) : "l"(ua), "l"(ub), "l"(uc));
    return *reinterpret_cast<float2*>(&ud);
}
__device__ __forceinline__ float2 dup2(float s) { return make_float2(s, s); }

__device__ __forceinline__ void cp_async16(void* smem_dst, const void* gmem_src) {
    unsigned s = (unsigned)__cvta_generic_to_shared(smem_dst);
    asm volatile("cp.async.cg.shared.global [%0], [%1], 16;\n" :: "r"(s), "l"(gmem_src));
}
__device__ __forceinline__ void cp_commit() { asm volatile("cp.async.commit_group;\n"); }
template <int N> __device__ __forceinline__ void cp_wait() {
    asm volatile("cp.async.wait_group %0;\n" :: "n"(N));
}

__device__ __forceinline__ void mbar_init(uint32_t mb, uint32_t count) {
    asm volatile("mbarrier.init.shared.b64 [%0], %1;" :: "r"(mb), "r"(count) : "memory");
}
__device__ __forceinline__ void mbar_expect_tx(uint32_t mb, uint32_t bytes) {
    asm volatile("mbarrier.arrive.expect_tx.shared.b64 _, [%0], %1;" :: "r"(mb), "r"(bytes) : "memory");
}
__device__ __forceinline__ void mbar_arrive(uint32_t mb) {
    asm volatile("mbarrier.arrive.shared.b64 _, [%0];" :: "r"(mb) : "memory");
}
__device__ __forceinline__ void bulk_g2s(uint32_t dst_smem, const void* src, uint32_t bytes, uint32_t mb) {
    asm volatile("cp.async.bulk.shared::cluster.global.mbarrier::complete_tx::bytes [%0], [%1], %2, [%3];"
                 :: "r"(dst_smem), "l"(src), "r"(bytes), "r"(mb) : "memory");
}
__device__ __forceinline__ void mbar_wait(uint32_t mb, int ph) {
    asm volatile(
        "{\n\t"
        ".reg .pred P;\n\t"
        "W%=:\n\t"
        "mbarrier.try_wait.parity.acquire.cta.shared::cta.b64 P, [%0], %1, 0x989680;\n\t"
        "@P bra D%=;\n\t"
        "bra W%=;\n\t"
        "D%=:\n\t"
        "}" :: "r"(mb), "r"(ph) : "memory");
}

__device__ __forceinline__ unsigned ld_acq_gpu(const unsigned* p) {
    unsigned v;
    asm volatile("ld.acquire.gpu.global.u32 %0, [%1];" : "=r"(v) : "l"(p) : "memory");
    return v;
}
__device__ __forceinline__ void bar_named(int id, int cnt) {
    asm volatile("bar.sync %0, %1;" :: "r"(id), "r"(cnt) : "memory");
}

__device__ __forceinline__ void ldsm_x4(uint32_t& r0, uint32_t& r1, uint32_t& r2, uint32_t& r3, uint32_t addr) {
    asm volatile("ldmatrix.sync.aligned.m8n8.x4.shared.b16 {%0,%1,%2,%3}, [%4];"
                 : "=r"(r0), "=r"(r1), "=r"(r2), "=r"(r3) : "r"(addr));
}
__device__ __forceinline__ void ldsm_x4_trans(uint32_t& r0, uint32_t& r1, uint32_t& r2, uint32_t& r3, uint32_t addr) {
    asm volatile("ldmatrix.sync.aligned.m8n8.x4.trans.shared.b16 {%0,%1,%2,%3}, [%4];"
                 : "=r"(r0), "=r"(r1), "=r"(r2), "=r"(r3) : "r"(addr));
}
__device__ __forceinline__ void ldsm_x2_trans(uint32_t& r0, uint32_t& r1, uint32_t addr) {
    asm volatile("ldmatrix.sync.aligned.m8n8.x2.trans.shared.b16 {%0,%1}, [%2];"
                 : "=r"(r0), "=r"(r1) : "r"(addr));
}
__device__ __forceinline__ void mma16816(float& d0, float& d1, float& d2, float& d3,
                                         uint32_t a0, uint32_t a1, uint32_t a2, uint32_t a3,
                                         uint32_t b0, uint32_t b1) {
    asm volatile("mma.sync.aligned.m16n8k16.row.col.f32.f16.f16.f32 "
                 "{%0,%1,%2,%3}, {%4,%5,%6,%7}, {%8,%9}, {%0,%1,%2,%3};"
                 : "+f"(d0), "+f"(d1), "+f"(d2), "+f"(d3)
                 : "r"(a0), "r"(a1), "r"(a2), "r"(a3), "r"(b0), "r"(b1));
}

// ---------------------------------------------------------------- reset: zero flags (stream-ordered before rec)
__global__ void reset_kernel() {
    for (int i = threadIdx.x; i < 4 * 32 * 32; i += blockDim.x) g_flag[i] = 0u;
}

// ---------------------------------------------------------------- Wout -> fp16
__global__ void wcvt_kernel(const float* __restrict__ Wout) {
    int i = blockIdx.x * 256 + threadIdx.x;
    g_Wouth[i] = __float2half_rn(Wout[i]);
}

// ---------------------------------------------------------------- Kernel A: Z[t][b][h] = b[h] + sum_f x[b][f][t] * Wx[f][h]
__global__ void __launch_bounds__(256, 2) zmat_kernel(const float* __restrict__ x,
                                                      const float* __restrict__ Wx,
                                                      const float* __restrict__ bias) {
    extern __shared__ float dsm[];
    float* xs = dsm;           // [2][32][128]
    float* ws = dsm + 8192;    // [2][32][128]
    int t0 = blockIdx.x * 128;
    int h0 = blockIdx.y * 128;
    int b  = blockIdx.z;
    int tid = threadIdx.x;
    int tt = tid >> 4;
    int th = tid & 15;
    const float* xb = x + (size_t)b * FF * TT;

    float2 acc[8][4];
    #pragma unroll
    for (int i = 0; i < 8; i++)
        #pragma unroll
        for (int j = 0; j < 4; j++) acc[i][j] = make_float2(0.f, 0.f);

    auto issue = [&](int ci, int buf) {
        int f0 = ci * 32;
        float* xd = xs + buf * 4096;
        float* wd = ws + buf * 4096;
        #pragma unroll
        for (int it = 0; it < 4; it++) {
            int idx = it * 256 + tid;
            int f = idx >> 5, u = (idx & 31) * 4;
            cp_async16(xd + f * 128 + u, xb + (f0 + f) * TT + t0 + u);
            cp_async16(wd + f * 128 + u, Wx + (f0 + f) * HH + h0 + u);
        }
        cp_commit();
    };

    issue(0, 0);
    for (int ci = 0; ci < 8; ci++) {
        if (ci < 7) { issue(ci + 1, (ci + 1) & 1); cp_wait<1>(); }
        else cp_wait<0>();
        __syncthreads();
        const float* xc = xs + (ci & 1) * 4096;
        const float* wc = ws + (ci & 1) * 4096;
        #pragma unroll
        for (int k = 0; k < 32; k++) {
            float4 a0 = *reinterpret_cast<const float4*>(xc + k * 128 + tt * 8);
            float4 a1 = *reinterpret_cast<const float4*>(xc + k * 128 + tt * 8 + 4);
            float4 w0 = *reinterpret_cast<const float4*>(wc + k * 128 + th * 8);
            float4 w1 = *reinterpret_cast<const float4*>(wc + k * 128 + th * 8 + 4);
            float2 wp[4] = { make_float2(w0.x, w0.y), make_float2(w0.z, w0.w),
                             make_float2(w1.x, w1.y), make_float2(w1.z, w1.w) };
            float av[8] = { a0.x, a0.y, a0.z, a0.w, a1.x, a1.y, a1.z, a1.w };
            #pragma unroll
            for (int i = 0; i < 8; i++) {
                float2 ad = dup2(av[i]);
                #pragma unroll
                for (int j = 0; j < 4; j++) acc[i][j] = ffma2(ad, wp[j], acc[i][j]);
            }
        }
        __syncthreads();
    }
    float4 bv0 = *reinterpret_cast<const float4*>(bias + h0 + th * 8);
    float4 bv1 = *reinterpret_cast<const float4*>(bias + h0 + th * 8 + 4);
    #pragma unroll
    for (int i = 0; i < 8; i++) {
        int t = t0 + tt * 8 + i;
        float* zp = g_Z + (size_t)t * (BB * HH) + b * HH + h0 + th * 8;
        float4 o0 = make_float4(acc[i][0].x + bv0.x, acc[i][0].y + bv0.y,
                                acc[i][1].x + bv0.z, acc[i][1].y + bv0.w);
        float4 o1 = make_float4(acc[i][2].x + bv1.x, acc[i][2].y + bv1.y,
                                acc[i][3].x + bv1.z, acc[i][3].y + bv1.w);
        *reinterpret_cast<float4*>(zp)     = o0;
        *reinterpret_cast<float4*>(zp + 4) = o1;
    }
}

// ---------------------------------------------------------------- Kernel B: persistent recurrence — HMMA (mma.sync fp16) + dataflow
// 128 CTAs: (r: 16 batch rows) x (c: 32 H cols). 384 threads: warps 0-7 compute (K-split
// 128 k each), warps 8-11 stagers. Wh fp16 B-fragments preloaded into REGISTERS once.
__global__ void __launch_bounds__(384, 1) rnn_rec_kernel(const float* __restrict__ Wh) {
    extern __shared__ float smem[];
    // [0..16 floats): 8 mbarriers: full[4] @ +0, consumed[4] @ +32B
    __half* wh_h = reinterpret_cast<__half*>(smem + 16);        // [1024][32] halfs (64KB), init-only
    __half* st_h = reinterpret_cast<__half*>(smem + 16 + 16384);// [1024][16] halfs (32KB)
    float*  red_s = smem + 16 + 16384 + 8192;                   // [8][512] floats (16KB)
    float*  fin   = red_s + 4096;                               // [16][33] floats
    uint32_t mbar0 = (uint32_t)__cvta_generic_to_shared(smem);
    uint32_t st_base = (uint32_t)__cvta_generic_to_shared(st_h);
    uint32_t wh_base = (uint32_t)__cvta_generic_to_shared(wh_h);

    int tid  = threadIdx.x;
    int wid  = tid >> 5, lane = tid & 31;
    int c = blockIdx.x & 31;                // column tile (32 cols)
    int r = blockIdx.x >> 5;                // batch row group (16 rows)
    int r16 = r * 16;

    if (tid == 0) {
        #pragma unroll
        for (int ch = 0; ch < 4; ch++) {
            mbar_init(mbar0 + ch * 8, 1);        // full: TMA expect_tx
            mbar_init(mbar0 + 32 + ch * 8, 2);   // consumed: 2 compute warps arrive
        }
    }
    // Wh tile -> fp16 SMEM [k][32]
    for (int i = tid; i < 32768; i += 384) {
        int k = i >> 5, n = i & 31;
        wh_h[i] = __float2half_rn(Wh[k * HH + c * 32 + n]);
    }
    __syncthreads();   // last block-wide sync; warps diverge below

    unsigned* myflag = &g_flag[(r * 32 + c) * 32];

    if (wid >= 8) {
        // ---------------- stager warps: one chunk each, free-running
        int ch = wid - 8;
        uint32_t fullmb = mbar0 + ch * 8;
        uint32_t consmb = mbar0 + 32 + ch * 8;
        const unsigned* pf = &g_flag[(r * 32 + ch * 8 + (lane & 7)) * 32];
        for (int t = 1; t < TT; ++t) {
            if (t >= 2) mbar_wait(consmb, t & 1);          // reads of step t-1 done
            if (lane < 8) {
                while (ld_acq_gpu(pf) < (unsigned)t) { }
            }
            __syncwarp();
            if (lane == 0) {
                asm volatile("fence.proxy.async;" ::: "memory");
                const __half* src = g_ST2h[(t + 1) & 1][r] + ch * 4096;   // 4096 halfs = 8KB
                mbar_expect_tx(fullmb, 8192u);
                uint32_t dst = (uint32_t)__cvta_generic_to_shared(st_h + ch * 4096);
                bulk_g2s(dst, src, 8192u, fullmb);
            }
        }
        return;
    }

    // ---------------- compute warps (threads 0..255), warp w owns k in [w*128, (w+1)*128)
    int w = wid;
    int ch = w >> 1;                       // chunk (256 k) this warp's slice lives in
    uint32_t fullmb = mbar0 + ch * 8;
    uint32_t consmb = mbar0 + 32 + ch * 8;

    // Preload B fragments (Wh^T tiles) into registers: 8 k-tiles x 4 n-tiles x 2 regs.
    uint32_t Bf[8][4][2];
    {
        int brow = ((lane >> 3) & 1) * 8 + (lane & 7);
        #pragma unroll
        for (int kt = 0; kt < 8; kt++) {
            int krow = w * 128 + kt * 16 + brow;
            #pragma unroll
            for (int nt = 0; nt < 4; nt++) {
                uint32_t addr = wh_base + (uint32_t)(krow * 32 + nt * 8) * 2;
                ldsm_x2_trans(Bf[kt][nt][0], Bf[kt][nt][1], addr);
            }
        }
    }

    // A ldmatrix (x4.trans from [k][16b]) address pattern
    int arow = ((lane >> 4) & 1) * 8 + (lane & 7);
    int acol = ((lane >> 3) & 1) * 8;

    // epilogue mapping: 2 outputs per thread
    int o  = tid * 2;
    int em = o >> 5, en = o & 31;
    int brow2 = r16 + em, hcol = c * 32 + en;
    int j2 = tid * 2;
    int hl = j2 >> 4, em2 = j2 & 15;

    // D-frag store mapping
    int m0 = lane >> 2;
    int nc = (lane & 3) * 2;

    float* zbase = g_Z + (size_t)brow2 * HH + hcol;

    for (int t = 0; t < TT; ++t) {
        float2 zq = *reinterpret_cast<const float2*>(zbase + (size_t)t * (BB * HH));

        float d[4][4];
        #pragma unroll
        for (int nt = 0; nt < 4; nt++)
            #pragma unroll
            for (int j = 0; j < 4; j++) d[nt][j] = 0.f;

        if (t > 0) {
            mbar_wait(fullmb, (t - 1) & 1);
            #pragma unroll
            for (int kt = 0; kt < 8; kt++) {
                uint32_t a0, a1, a2, a3;
                uint32_t addr = st_base + (uint32_t)((w * 128 + kt * 16 + arow) * 16 + acol) * 2;
                ldsm_x4_trans(a0, a1, a2, a3, addr);
                #pragma unroll
                for (int nt = 0; nt < 4; nt++)
                    mma16816(d[nt][0], d[nt][1], d[nt][2], d[nt][3],
                             a0, a1, a2, a3, Bf[kt][nt][0], Bf[kt][nt][1]);
            }
            __syncwarp();
            if (lane == 0) mbar_arrive(consmb);   // chunk readable -> overwritable by stager
        }

        // partials: red_s[w][m*32 + n]
        {
            float* rp = red_s + w * 512;
            #pragma unroll
            for (int nt = 0; nt < 4; nt++) {
                *reinterpret_cast<float2*>(rp + m0 * 32 + nt * 8 + nc)       = make_float2(d[nt][0], d[nt][1]);
                *reinterpret_cast<float2*>(rp + (m0 + 8) * 32 + nt * 8 + nc) = make_float2(d[nt][2], d[nt][3]);
            }
        }
        bar_named(1, 256);
        float s0, s1;
        {
            float2 v = make_float2(0.f, 0.f);
            #pragma unroll
            for (int ww = 0; ww < 8; ww++) {
                float2 p = *reinterpret_cast<const float2*>(red_s + ww * 512 + o);
                v.x += p.x; v.y += p.y;
            }
            s0 = tanhf(zq.x + v.x);
            s1 = tanhf(zq.y + v.y);
            fin[em * 33 + en]     = s0;
            fin[em * 33 + en + 1] = s1;
        }
        bar_named(1, 256);
        {
            // coalesced transposed fp16 state store
            float a  = fin[em2 * 33 + hl];
            float b2 = fin[(em2 + 1) * 33 + hl];
            __half2* stp = reinterpret_cast<__half2*>(g_ST2h[t & 1][r] + (size_t)(c * 32 + hl) * 16 + em2);
            *stp = __floats2half2_rn(a, b2);
        }
        bar_named(1, 256);    // all state stores ordered before release
        if (tid == 0) {
            asm volatile("fence.acq_rel.gpu;" ::: "memory");
            unsigned g = (unsigned)(t + 1);
            asm volatile("st.relaxed.gpu.global.u32 [%0], %1;" :: "l"(myflag), "r"(g) : "memory");
        }
        // fp16 row-major states for out_kernel (off inter-CTA critical path)
        __half2* shp = reinterpret_cast<__half2*>(g_Sh + ((size_t)t * BB + brow2) * HH + hcol);
        *shp = __floats2half2_rn(s0, s1);
    }
}

// ---------------------------------------------------------------- Kernel C: out = S(fp16) @ Wout(fp16) + bout, HMMA
// 128 rows x 128 cols per CTA, 256 threads, warp w owns 16 n-cols; K=1024 in 32-chunks,
// double-buffered cp.async; padded SMEM (A rows 40h, B rows 136h) => conflict-free ldmatrix.
__global__ void __launch_bounds__(256, 1) out_kernel(const float* __restrict__ bout,
                                                     float* __restrict__ out) {
    extern __shared__ __half hsm[];
    __half* As = hsm;                 // [2][128][40]
    __half* Bs = hsm + 2 * 128 * 40;  // [2][32][136]
    int o0 = blockIdx.x * 128;
    int r0 = blockIdx.y * 128;
    int tid = threadIdx.x;
    int w = tid >> 5, lane = tid & 31;

    float d[8][2][4];
    #pragma unroll
    for (int mt = 0; mt < 8; mt++)
        #pragma unroll
        for (int nt = 0; nt < 2; nt++)
            #pragma unroll
            for (int j = 0; j < 4; j++) d[mt][nt][j] = 0.f;

    auto issue = [&](int ci, int buf) {
        int f0 = ci * 32;
        __half* Ad = As + buf * 5120;
        __half* Bd = Bs + buf * 4352;
        #pragma unroll
        for (int it = 0; it < 2; it++) {
            int idx = it * 256 + tid;                  // 0..511
            int row = idx >> 2, seg = idx & 3;         // A: 128 rows x 4 x 16B
            cp_async16(Ad + row * 40 + seg * 8, g_Sh + (size_t)(r0 + row) * HH + f0 + seg * 8);
            int kr = idx >> 4, sg = idx & 15;          // B: 32 rows x 16 x 16B
            cp_async16(Bd + kr * 136 + sg * 8, g_Wouth + (size_t)(f0 + kr) * OO + o0 + sg * 8);
        }
        cp_commit();
    };

    int brow = ((lane >> 3) & 1) * 8 + (lane & 7);     // B ldsm row pattern (lanes 0-15)
    int amr = lane & 15;                               // A ldsm: row within m16
    int akc = (lane >> 4) * 8;                         // A ldsm: k-col offset for groups 2,3

    issue(0, 0);
    for (int ci = 0; ci < 32; ci++) {
        if (ci < 31) { issue(ci + 1, (ci + 1) & 1); cp_wait<1>(); }
        else cp_wait<0>();
        __syncthreads();
        const __half* Ac = As + (ci & 1) * 5120;
        const __half* Bc = Bs + (ci & 1) * 4352;
        uint32_t a_base = (uint32_t)__cvta_generic_to_shared(Ac);
        uint32_t b_base = (uint32_t)__cvta_generic_to_shared(Bc);
        #pragma unroll
        for (int kt = 0; kt < 2; kt++) {
            uint32_t Bf[2][2];
            #pragma unroll
            for (int nt = 0; nt < 2; nt++) {
                uint32_t baddr = b_base + (uint32_t)((kt * 16 + brow) * 136 + w * 16 + nt * 8) * 2;
                ldsm_x2_trans(Bf[nt][0], Bf[nt][1], baddr);
            }
            #pragma unroll
            for (int mt = 0; mt < 8; mt++) {
                uint32_t a0, a1, a2, a3;
                uint32_t aaddr = a_base + (uint32_t)((mt * 16 + amr) * 40 + kt * 16 + akc) * 2;
                ldsm_x4(a0, a1, a2, a3, aaddr);
                mma16816(d[mt][0][0], d[mt][0][1], d[mt][0][2], d[mt][0][3],
                         a0, a1, a2, a3, Bf[0][0], Bf[0][1]);
                mma16816(d[mt][1][0], d[mt][1][1], d[mt][1][2], d[mt][1][3],
                         a0, a1, a2, a3, Bf[1][0], Bf[1][1]);
            }
        }
        __syncthreads();
    }

    // epilogue: direct fragment stores (float2, 8B aligned, quad-coalesced)
    int nc = (lane & 3) * 2;
    int mrow = lane >> 2;
    #pragma unroll
    for (int nt = 0; nt < 2; nt++) {
        int col = o0 + w * 16 + nt * 8 + nc;
        float2 bv = *reinterpret_cast<const float2*>(bout + col);
        #pragma unroll
        for (int mt = 0; mt < 8; mt++) {
            int g0 = r0 + mt * 16 + mrow;
            int g1 = g0 + 8;
            int t0r = g0 >> 6, b0r = g0 & 63;
            int t1r = g1 >> 6, b1r = g1 & 63;
            *reinterpret_cast<float2*>(out + (size_t)b0r * (TT * OO) + t0r * OO + col) =
                make_float2(d[mt][nt][0] + bv.x, d[mt][nt][1] + bv.y);
            *reinterpret_cast<float2*>(out + (size_t)b1r * (TT * OO) + t1r * OO + col) =
                make_float2(d[mt][nt][2] + bv.x, d[mt][nt][3] + bv.y);
        }
    }
}

// ---------------------------------------------------------------- launch
extern "C" void kernel_launch(void* const* d_in, const int* in_sizes, int n_in,
                              void* d_out, int out_size) {
    const float* x    = (const float*)d_in[0];   // (B,F,T)
    const float* Wx   = (const float*)d_in[1];   // (F,H)
    const float* Wh   = (const float*)d_in[2];   // (H,H)
    const float* bv   = (const float*)d_in[3];   // (H,)
    const float* Wout = (const float*)d_in[4];   // (H,O)
    const float* bo   = (const float*)d_in[5];   // (O,)
    float* out = (float*)d_out;                  // (B,T,O)

    (void)in_sizes; (void)n_in; (void)out_size;

    // Phase 0: reset dataflow flags + convert Wout to fp16
    reset_kernel<<<1, 256>>>();
    wcvt_kernel<<<(HH * OO) / 256, 256>>>(Wout);

    // Phase 1: Z = x@Wx + b (128x128 tiles, 8x8/thread, 2 CTAs/SM)
    cudaFuncSetAttribute(zmat_kernel, cudaFuncAttributeMaxDynamicSharedMemorySize, 65536);
    dim3 ga(TT / 128, HH / 128, BB);
    zmat_kernel<<<ga, 256, 65536>>>(x, Wx, bv);

    // Phase 2: persistent recurrence (HMMA fp16, warp-specialized dataflow)
    size_t dyn = (size_t)(16 + 16384 + 8192 + 4096 + 528) * sizeof(float);  // 116864 B
    cudaFuncSetAttribute(rnn_rec_kernel, cudaFuncAttributeMaxDynamicSharedMemorySize, 232448);
    rnn_rec_kernel<<<NB, 384, dyn>>>(Wh);

    // Phase 3: output projection (HMMA fp16, 128x128 tiles)
    size_t osm = (2 * 128 * 40 + 2 * 32 * 136) * sizeof(__half);  // 37888 B
    cudaFuncSetAttribute(out_kernel, cudaFuncAttributeMaxDynamicSharedMemorySize, (int)osm);
    dim3 gc(OO / 128, (TT * BB) / 128);   // n-inner for A-tile L2 reuse
    out_kernel<<<gc, 256, osm>>>(bo, out);
}

// round 14
// speedup vs baseline: 2.6459x; 1.1449x over previous
#include <cuda_runtime.h>
#include <cuda_bf16.h>
#include <cuda_fp16.h>
#include <math.h>
#include <stdint.h>

#define BB 64
#define FF 256
#define TT 1024
#define HH 1024
#define OO 512
#define NB 128   // persistent CTAs: 4 batch-row groups x 32 H-col tiles

// Scratch (allocation-free rule: __device__ globals)
__device__ float  g_Z[(size_t)TT * BB * HH];    // Z = x@Wx + b, [t][b][h] (fp32, read by rec)
__device__ __half g_Sh[(size_t)TT * BB * HH];   // fp16 states row-major [t*64+b][h] (feeds out_kernel)
__device__ __half g_ST2h[2][4][HH * 16];        // fp16 transposed state ping-pong, [buf][r-group][h][16 b]
__device__ __half g_Wouth[HH * OO];             // fp16 Wout
__device__ __half g_Wxh[FF * HH];               // fp16 Wx
__device__ __half g_xh[(size_t)BB * FF * TT];   // fp16 x, [b][f][t]
__device__ unsigned g_flag[4 * 32 * 32];        // per-(r,c) generation flags, 128B apart

// ---------------------------------------------------------------- helpers
__device__ __forceinline__ void cp_async16(void* smem_dst, const void* gmem_src) {
    unsigned s = (unsigned)__cvta_generic_to_shared(smem_dst);
    asm volatile("cp.async.cg.shared.global [%0], [%1], 16;\n" :: "r"(s), "l"(gmem_src));
}
__device__ __forceinline__ void cp_commit() { asm volatile("cp.async.commit_group;\n"); }
template <int N> __device__ __forceinline__ void cp_wait() {
    asm volatile("cp.async.wait_group %0;\n" :: "n"(N));
}

__device__ __forceinline__ void mbar_init(uint32_t mb, uint32_t count) {
    asm volatile("mbarrier.init.shared.b64 [%0], %1;" :: "r"(mb), "r"(count) : "memory");
}
__device__ __forceinline__ void mbar_expect_tx(uint32_t mb, uint32_t bytes) {
    asm volatile("mbarrier.arrive.expect_tx.shared.b64 _, [%0], %1;" :: "r"(mb), "r"(bytes) : "memory");
}
__device__ __forceinline__ void mbar_arrive(uint32_t mb) {
    asm volatile("mbarrier.arrive.shared.b64 _, [%0];" :: "r"(mb) : "memory");
}
__device__ __forceinline__ void bulk_g2s(uint32_t dst_smem, const void* src, uint32_t bytes, uint32_t mb) {
    asm volatile("cp.async.bulk.shared::cluster.global.mbarrier::complete_tx::bytes [%0], [%1], %2, [%3];"
                 :: "r"(dst_smem), "l"(src), "r"(bytes), "r"(mb) : "memory");
}
__device__ __forceinline__ void mbar_wait(uint32_t mb, int ph) {
    asm volatile(
        "{\n\t"
        ".reg .pred P;\n\t"
        "W%=:\n\t"
        "mbarrier.try_wait.parity.acquire.cta.shared::cta.b64 P, [%0], %1, 0x989680;\n\t"
        "@P bra D%=;\n\t"
        "bra W%=;\n\t"
        "D%=:\n\t"
        "}" :: "r"(mb), "r"(ph) : "memory");
}

__device__ __forceinline__ unsigned ld_acq_gpu(const unsigned* p) {
    unsigned v;
    asm volatile("ld.acquire.gpu.global.u32 %0, [%1];" : "=r"(v) : "l"(p) : "memory");
    return v;
}
__device__ __forceinline__ void bar_named(int id, int cnt) {
    asm volatile("bar.sync %0, %1;" :: "r"(id), "r"(cnt) : "memory");
}

__device__ __forceinline__ void ldsm_x4(uint32_t& r0, uint32_t& r1, uint32_t& r2, uint32_t& r3, uint32_t addr) {
    asm volatile("ldmatrix.sync.aligned.m8n8.x4.shared.b16 {%0,%1,%2,%3}, [%4];"
                 : "=r"(r0), "=r"(r1), "=r"(r2), "=r"(r3) : "r"(addr));
}
__device__ __forceinline__ void ldsm_x4_trans(uint32_t& r0, uint32_t& r1, uint32_t& r2, uint32_t& r3, uint32_t addr) {
    asm volatile("ldmatrix.sync.aligned.m8n8.x4.trans.shared.b16 {%0,%1,%2,%3}, [%4];"
                 : "=r"(r0), "=r"(r1), "=r"(r2), "=r"(r3) : "r"(addr));
}
__device__ __forceinline__ void ldsm_x2_trans(uint32_t& r0, uint32_t& r1, uint32_t addr) {
    asm volatile("ldmatrix.sync.aligned.m8n8.x2.trans.shared.b16 {%0,%1}, [%2];"
                 : "=r"(r0), "=r"(r1) : "r"(addr));
}
__device__ __forceinline__ void mma16816(float& d0, float& d1, float& d2, float& d3,
                                         uint32_t a0, uint32_t a1, uint32_t a2, uint32_t a3,
                                         uint32_t b0, uint32_t b1) {
    asm volatile("mma.sync.aligned.m16n8k16.row.col.f32.f16.f16.f32 "
                 "{%0,%1,%2,%3}, {%4,%5,%6,%7}, {%8,%9}, {%0,%1,%2,%3};"
                 : "+f"(d0), "+f"(d1), "+f"(d2), "+f"(d3)
                 : "r"(a0), "r"(a1), "r"(a2), "r"(a3), "r"(b0), "r"(b1));
}

// ---------------------------------------------------------------- small prep kernels
__global__ void reset_kernel() {
    for (int i = threadIdx.x; i < 4 * 32 * 32; i += blockDim.x) g_flag[i] = 0u;
}
__global__ void wcvt_kernel(const float* __restrict__ Wout) {
    int i = blockIdx.x * 256 + threadIdx.x;
    g_Wouth[i] = __float2half_rn(Wout[i]);
}
__global__ void wxcvt_kernel(const float* __restrict__ Wx) {
    int i = blockIdx.x * 256 + threadIdx.x;
    g_Wxh[i] = __float2half_rn(Wx[i]);
}
__global__ void xcvt_kernel(const float* __restrict__ x) {
    size_t i = ((size_t)blockIdx.x * 256 + threadIdx.x) * 4;
    float4 v = *reinterpret_cast<const float4*>(x + i);
    __half2* p = reinterpret_cast<__half2*>(g_xh + i);
    p[0] = __floats2half2_rn(v.x, v.y);
    p[1] = __floats2half2_rn(v.z, v.w);
}

// ---------------------------------------------------------------- Kernel A: Z[t][b][h] = b[h] + sum_f x[b][f][t] * Wx[f][h]  (HMMA fp16)
// Per CTA: 128 t-rows x 128 h-cols, K=F=256 in 8 chunks of 32, double-buffered cp.async.
// A staged [f][t] (k-major) -> ldsm_x4_trans (rec-validated pattern, stride 136);
// B staged [f][h] (k-major) -> ldsm_x2_trans (out_kernel-validated pattern).
__global__ void __launch_bounds__(256, 2) zmat_kernel(const float* __restrict__ bias) {
    extern __shared__ __half hsm[];
    __half* As = hsm;                 // [2][32][136]
    __half* Bs = hsm + 2 * 32 * 136;  // [2][32][136]
    int h0 = blockIdx.x * 128;
    int t0 = blockIdx.y * 128;
    int b  = blockIdx.z;
    int tid = threadIdx.x;
    int w = tid >> 5, lane = tid & 31;

    float d[8][2][4];
    #pragma unroll
    for (int mt = 0; mt < 8; mt++)
        #pragma unroll
        for (int nt = 0; nt < 2; nt++)
            #pragma unroll
            for (int j = 0; j < 4; j++) d[mt][nt][j] = 0.f;

    auto issue = [&](int ci, int buf) {
        int f0 = ci * 32;
        __half* Ad = As + buf * 4352;
        __half* Bd = Bs + buf * 4352;
        #pragma unroll
        for (int it = 0; it < 2; it++) {
            int idx = it * 256 + tid;              // 0..511: 32 rows x 16 x 16B each
            int f = idx >> 4, sg = idx & 15;
            cp_async16(Ad + f * 136 + sg * 8, g_xh + ((size_t)b * FF + f0 + f) * TT + t0 + sg * 8);
            cp_async16(Bd + f * 136 + sg * 8, g_Wxh + (size_t)(f0 + f) * HH + h0 + sg * 8);
        }
        cp_commit();
    };

    int brow = ((lane >> 3) & 1) * 8 + (lane & 7);
    int arow = ((lane >> 4) & 1) * 8 + (lane & 7);
    int acol = ((lane >> 3) & 1) * 8;

    issue(0, 0);
    for (int ci = 0; ci < 8; ci++) {
        if (ci < 7) { issue(ci + 1, (ci + 1) & 1); cp_wait<1>(); }
        else cp_wait<0>();
        __syncthreads();
        uint32_t a_base = (uint32_t)__cvta_generic_to_shared(As + (ci & 1) * 4352);
        uint32_t b_base = (uint32_t)__cvta_generic_to_shared(Bs + (ci & 1) * 4352);
        #pragma unroll
        for (int kt = 0; kt < 2; kt++) {
            uint32_t Bf[2][2];
            #pragma unroll
            for (int nt = 0; nt < 2; nt++) {
                uint32_t baddr = b_base + (uint32_t)((kt * 16 + brow) * 136 + w * 16 + nt * 8) * 2;
                ldsm_x2_trans(Bf[nt][0], Bf[nt][1], baddr);
            }
            #pragma unroll
            for (int mt = 0; mt < 8; mt++) {
                uint32_t a0, a1, a2, a3;
                uint32_t aaddr = a_base + (uint32_t)((kt * 16 + arow) * 136 + mt * 16 + acol) * 2;
                ldsm_x4_trans(a0, a1, a2, a3, aaddr);
                mma16816(d[mt][0][0], d[mt][0][1], d[mt][0][2], d[mt][0][3],
                         a0, a1, a2, a3, Bf[0][0], Bf[0][1]);
                mma16816(d[mt][1][0], d[mt][1][1], d[mt][1][2], d[mt][1][3],
                         a0, a1, a2, a3, Bf[1][0], Bf[1][1]);
            }
        }
        __syncthreads();
    }

    // epilogue: Z[t][b][h] fp32 + bias (float2, quad-coalesced)
    int nc = (lane & 3) * 2;
    int mrow = lane >> 2;
    #pragma unroll
    for (int nt = 0; nt < 2; nt++) {
        int col = h0 + w * 16 + nt * 8 + nc;
        float2 bv = *reinterpret_cast<const float2*>(bias + col);
        #pragma unroll
        for (int mt = 0; mt < 8; mt++) {
            int ta = t0 + mt * 16 + mrow;
            int tb = ta + 8;
            *reinterpret_cast<float2*>(g_Z + ((size_t)ta * BB + b) * HH + col) =
                make_float2(d[mt][nt][0] + bv.x, d[mt][nt][1] + bv.y);
            *reinterpret_cast<float2*>(g_Z + ((size_t)tb * BB + b) * HH + col) =
                make_float2(d[mt][nt][2] + bv.x, d[mt][nt][3] + bv.y);
        }
    }
}

// ---------------------------------------------------------------- Kernel B: persistent recurrence — HMMA (mma.sync fp16) + dataflow
// 128 CTAs: (r: 16 batch rows) x (c: 32 H cols). 384 threads: warps 0-7 compute (K-split
// 128 k each), warps 8-11 stagers. Wh fp16 B-fragments preloaded into REGISTERS once.
__global__ void __launch_bounds__(384, 1) rnn_rec_kernel(const float* __restrict__ Wh) {
    extern __shared__ float smem[];
    // [0..16 floats): 8 mbarriers: full[4] @ +0, consumed[4] @ +32B
    __half* wh_h = reinterpret_cast<__half*>(smem + 16);        // [1024][32] halfs (64KB), init-only
    __half* st_h = reinterpret_cast<__half*>(smem + 16 + 16384);// [1024][16] halfs (32KB)
    float*  red_s = smem + 16 + 16384 + 8192;                   // [8][512] floats (16KB)
    float*  fin   = red_s + 4096;                               // [16][33] floats
    uint32_t mbar0 = (uint32_t)__cvta_generic_to_shared(smem);
    uint32_t st_base = (uint32_t)__cvta_generic_to_shared(st_h);
    uint32_t wh_base = (uint32_t)__cvta_generic_to_shared(wh_h);

    int tid  = threadIdx.x;
    int wid  = tid >> 5, lane = tid & 31;
    int c = blockIdx.x & 31;                // column tile (32 cols)
    int r = blockIdx.x >> 5;                // batch row group (16 rows)
    int r16 = r * 16;

    if (tid == 0) {
        #pragma unroll
        for (int ch = 0; ch < 4; ch++) {
            mbar_init(mbar0 + ch * 8, 1);        // full: TMA expect_tx
            mbar_init(mbar0 + 32 + ch * 8, 2);   // consumed: 2 compute warps arrive
        }
    }
    // Wh tile -> fp16 SMEM [k][32]
    for (int i = tid; i < 32768; i += 384) {
        int k = i >> 5, n = i & 31;
        wh_h[i] = __float2half_rn(Wh[k * HH + c * 32 + n]);
    }
    __syncthreads();   // last block-wide sync; warps diverge below

    unsigned* myflag = &g_flag[(r * 32 + c) * 32];

    if (wid >= 8) {
        // ---------------- stager warps: one chunk each, free-running
        int ch = wid - 8;
        uint32_t fullmb = mbar0 + ch * 8;
        uint32_t consmb = mbar0 + 32 + ch * 8;
        const unsigned* pf = &g_flag[(r * 32 + ch * 8 + (lane & 7)) * 32];
        for (int t = 1; t < TT; ++t) {
            if (t >= 2) mbar_wait(consmb, t & 1);          // reads of step t-1 done
            if (lane < 8) {
                while (ld_acq_gpu(pf) < (unsigned)t) { }
            }
            __syncwarp();
            if (lane == 0) {
                asm volatile("fence.proxy.async;" ::: "memory");
                const __half* src = g_ST2h[(t + 1) & 1][r] + ch * 4096;   // 4096 halfs = 8KB
                mbar_expect_tx(fullmb, 8192u);
                uint32_t dst = (uint32_t)__cvta_generic_to_shared(st_h + ch * 4096);
                bulk_g2s(dst, src, 8192u, fullmb);
            }
        }
        return;
    }

    // ---------------- compute warps (threads 0..255), warp w owns k in [w*128, (w+1)*128)
    int w = wid;
    int ch = w >> 1;                       // chunk (256 k) this warp's slice lives in
    uint32_t fullmb = mbar0 + ch * 8;
    uint32_t consmb = mbar0 + 32 + ch * 8;

    // Preload B fragments (Wh^T tiles) into registers: 8 k-tiles x 4 n-tiles x 2 regs.
    uint32_t Bf[8][4][2];
    {
        int brow = ((lane >> 3) & 1) * 8 + (lane & 7);
        #pragma unroll
        for (int kt = 0; kt < 8; kt++) {
            int krow = w * 128 + kt * 16 + brow;
            #pragma unroll
            for (int nt = 0; nt < 4; nt++) {
                uint32_t addr = wh_base + (uint32_t)(krow * 32 + nt * 8) * 2;
                ldsm_x2_trans(Bf[kt][nt][0], Bf[kt][nt][1], addr);
            }
        }
    }

    // A ldmatrix (x4.trans from [k][16b]) address pattern
    int arow = ((lane >> 4) & 1) * 8 + (lane & 7);
    int acol = ((lane >> 3) & 1) * 8;

    // epilogue mapping: 2 outputs per thread
    int o  = tid * 2;
    int em = o >> 5, en = o & 31;
    int brow2 = r16 + em, hcol = c * 32 + en;
    int j2 = tid * 2;
    int hl = j2 >> 4, em2 = j2 & 15;

    // D-frag store mapping
    int m0 = lane >> 2;
    int nc = (lane & 3) * 2;

    float* zbase = g_Z + (size_t)brow2 * HH + hcol;

    for (int t = 0; t < TT; ++t) {
        float2 zq = *reinterpret_cast<const float2*>(zbase + (size_t)t * (BB * HH));

        float d[4][4];
        #pragma unroll
        for (int nt = 0; nt < 4; nt++)
            #pragma unroll
            for (int j = 0; j < 4; j++) d[nt][j] = 0.f;

        if (t > 0) {
            mbar_wait(fullmb, (t - 1) & 1);
            #pragma unroll
            for (int kt = 0; kt < 8; kt++) {
                uint32_t a0, a1, a2, a3;
                uint32_t addr = st_base + (uint32_t)((w * 128 + kt * 16 + arow) * 16 + acol) * 2;
                ldsm_x4_trans(a0, a1, a2, a3, addr);
                #pragma unroll
                for (int nt = 0; nt < 4; nt++)
                    mma16816(d[nt][0], d[nt][1], d[nt][2], d[nt][3],
                             a0, a1, a2, a3, Bf[kt][nt][0], Bf[kt][nt][1]);
            }
            __syncwarp();
            if (lane == 0) mbar_arrive(consmb);   // chunk readable -> overwritable by stager
        }

        // partials: red_s[w][m*32 + n]
        {
            float* rp = red_s + w * 512;
            #pragma unroll
            for (int nt = 0; nt < 4; nt++) {
                *reinterpret_cast<float2*>(rp + m0 * 32 + nt * 8 + nc)       = make_float2(d[nt][0], d[nt][1]);
                *reinterpret_cast<float2*>(rp + (m0 + 8) * 32 + nt * 8 + nc) = make_float2(d[nt][2], d[nt][3]);
            }
        }
        bar_named(1, 256);
        float s0, s1;
        {
            float2 v = make_float2(0.f, 0.f);
            #pragma unroll
            for (int ww = 0; ww < 8; ww++) {
                float2 p = *reinterpret_cast<const float2*>(red_s + ww * 512 + o);
                v.x += p.x; v.y += p.y;
            }
            s0 = tanhf(zq.x + v.x);
            s1 = tanhf(zq.y + v.y);
            fin[em * 33 + en]     = s0;
            fin[em * 33 + en + 1] = s1;
        }
        bar_named(1, 256);
        {
            // coalesced transposed fp16 state store
            float a  = fin[em2 * 33 + hl];
            float b2 = fin[(em2 + 1) * 33 + hl];
            __half2* stp = reinterpret_cast<__half2*>(g_ST2h[t & 1][r] + (size_t)(c * 32 + hl) * 16 + em2);
            *stp = __floats2half2_rn(a, b2);
        }
        bar_named(1, 256);    // all state stores ordered before release
        if (tid == 0) {
            asm volatile("fence.acq_rel.gpu;" ::: "memory");
            unsigned g = (unsigned)(t + 1);
            asm volatile("st.relaxed.gpu.global.u32 [%0], %1;" :: "l"(myflag), "r"(g) : "memory");
        }
        // fp16 row-major states for out_kernel (off inter-CTA critical path)
        __half2* shp = reinterpret_cast<__half2*>(g_Sh + ((size_t)t * BB + brow2) * HH + hcol);
        *shp = __floats2half2_rn(s0, s1);
    }
}

// ---------------------------------------------------------------- Kernel C: out = S(fp16) @ Wout(fp16) + bout, HMMA
__global__ void __launch_bounds__(256, 1) out_kernel(const float* __restrict__ bout,
                                                     float* __restrict__ out) {
    extern __shared__ __half hsm[];
    __half* As = hsm;                 // [2][128][40]
    __half* Bs = hsm + 2 * 128 * 40;  // [2][32][136]
    int o0 = blockIdx.x * 128;
    int r0 = blockIdx.y * 128;
    int tid = threadIdx.x;
    int w = tid >> 5, lane = tid & 31;

    float d[8][2][4];
    #pragma unroll
    for (int mt = 0; mt < 8; mt++)
        #pragma unroll
        for (int nt = 0; nt < 2; nt++)
            #pragma unroll
            for (int j = 0; j < 4; j++) d[mt][nt][j] = 0.f;

    auto issue = [&](int ci, int buf) {
        int f0 = ci * 32;
        __half* Ad = As + buf * 5120;
        __half* Bd = Bs + buf * 4352;
        #pragma unroll
        for (int it = 0; it < 2; it++) {
            int idx = it * 256 + tid;                  // 0..511
            int row = idx >> 2, seg = idx & 3;         // A: 128 rows x 4 x 16B
            cp_async16(Ad + row * 40 + seg * 8, g_Sh + (size_t)(r0 + row) * HH + f0 + seg * 8);
            int kr = idx >> 4, sg = idx & 15;          // B: 32 rows x 16 x 16B
            cp_async16(Bd + kr * 136 + sg * 8, g_Wouth + (size_t)(f0 + kr) * OO + o0 + sg * 8);
        }
        cp_commit();
    };

    int brow = ((lane >> 3) & 1) * 8 + (lane & 7);
    int amr = lane & 15;
    int akc = (lane >> 4) * 8;

    issue(0, 0);
    for (int ci = 0; ci < 32; ci++) {
        if (ci < 31) { issue(ci + 1, (ci + 1) & 1); cp_wait<1>(); }
        else cp_wait<0>();
        __syncthreads();
        const __half* Ac = As + (ci & 1) * 5120;
        const __half* Bc = Bs + (ci & 1) * 4352;
        uint32_t a_base = (uint32_t)__cvta_generic_to_shared(Ac);
        uint32_t b_base = (uint32_t)__cvta_generic_to_shared(Bc);
        #pragma unroll
        for (int kt = 0; kt < 2; kt++) {
            uint32_t Bf[2][2];
            #pragma unroll
            for (int nt = 0; nt < 2; nt++) {
                uint32_t baddr = b_base + (uint32_t)((kt * 16 + brow) * 136 + w * 16 + nt * 8) * 2;
                ldsm_x2_trans(Bf[nt][0], Bf[nt][1], baddr);
            }
            #pragma unroll
            for (int mt = 0; mt < 8; mt++) {
                uint32_t a0, a1, a2, a3;
                uint32_t aaddr = a_base + (uint32_t)((mt * 16 + amr) * 40 + kt * 16 + akc) * 2;
                ldsm_x4(a0, a1, a2, a3, aaddr);
                mma16816(d[mt][0][0], d[mt][0][1], d[mt][0][2], d[mt][0][3],
                         a0, a1, a2, a3, Bf[0][0], Bf[0][1]);
                mma16816(d[mt][1][0], d[mt][1][1], d[mt][1][2], d[mt][1][3],
                         a0, a1, a2, a3, Bf[1][0], Bf[1][1]);
            }
        }
        __syncthreads();
    }

    int nc = (lane & 3) * 2;
    int mrow = lane >> 2;
    #pragma unroll
    for (int nt = 0; nt < 2; nt++) {
        int col = o0 + w * 16 + nt * 8 + nc;
        float2 bv = *reinterpret_cast<const float2*>(bout + col);
        #pragma unroll
        for (int mt = 0; mt < 8; mt++) {
            int g0 = r0 + mt * 16 + mrow;
            int g1 = g0 + 8;
            int t0r = g0 >> 6, b0r = g0 & 63;
            int t1r = g1 >> 6, b1r = g1 & 63;
            *reinterpret_cast<float2*>(out + (size_t)b0r * (TT * OO) + t0r * OO + col) =
                make_float2(d[mt][nt][0] + bv.x, d[mt][nt][1] + bv.y);
            *reinterpret_cast<float2*>(out + (size_t)b1r * (TT * OO) + t1r * OO + col) =
                make_float2(d[mt][nt][2] + bv.x, d[mt][nt][3] + bv.y);
        }
    }
}

// ---------------------------------------------------------------- launch
extern "C" void kernel_launch(void* const* d_in, const int* in_sizes, int n_in,
                              void* d_out, int out_size) {
    const float* x    = (const float*)d_in[0];   // (B,F,T)
    const float* Wx   = (const float*)d_in[1];   // (F,H)
    const float* Wh   = (const float*)d_in[2];   // (H,H)
    const float* bv   = (const float*)d_in[3];   // (H,)
    const float* Wout = (const float*)d_in[4];   // (H,O)
    const float* bo   = (const float*)d_in[5];   // (O,)
    float* out = (float*)d_out;                  // (B,T,O)

    (void)in_sizes; (void)n_in; (void)out_size;

    // Phase 0: reset flags + fp16 conversions (x, Wx, Wout)
    reset_kernel<<<1, 256>>>();
    wcvt_kernel<<<(HH * OO) / 256, 256>>>(Wout);
    wxcvt_kernel<<<(FF * HH) / 256, 256>>>(Wx);
    xcvt_kernel<<<(int)(((size_t)BB * FF * TT) / 1024), 256>>>(x);

    // Phase 1: Z = x@Wx + b (HMMA fp16, 128x128 tiles, 2 CTAs/SM)
    size_t zsm = (size_t)(2 * 32 * 136 * 2) * sizeof(__half);   // 34816 B
    cudaFuncSetAttribute(zmat_kernel, cudaFuncAttributeMaxDynamicSharedMemorySize, (int)zsm);
    dim3 ga(HH / 128, TT / 128, BB);
    zmat_kernel<<<ga, 256, zsm>>>(bv);

    // Phase 2: persistent recurrence (HMMA fp16, warp-specialized dataflow)
    size_t dyn = (size_t)(16 + 16384 + 8192 + 4096 + 528) * sizeof(float);  // 116864 B
    cudaFuncSetAttribute(rnn_rec_kernel, cudaFuncAttributeMaxDynamicSharedMemorySize, 232448);
    rnn_rec_kernel<<<NB, 384, dyn>>>(Wh);

    // Phase 3: output projection (HMMA fp16, 128x128 tiles)
    size_t osm = (2 * 128 * 40 + 2 * 32 * 136) * sizeof(__half);  // 37888 B
    cudaFuncSetAttribute(out_kernel, cudaFuncAttributeMaxDynamicSharedMemorySize, (int)osm);
    dim3 gc(OO / 128, (TT * BB) / 128);   // n-inner for A-tile L2 reuse
    out_kernel<<<gc, 256, osm>>>(bo, out);
}

// round 15
// speedup vs baseline: 2.6989x; 1.0200x over previous
#include <cuda_runtime.h>
#include <cuda_bf16.h>
#include <cuda_fp16.h>
#include <math.h>
#include <stdint.h>

#define BB 64
#define FF 256
#define TT 1024
#define HH 1024
#define OO 512
#define NB 128   // persistent CTAs: 4 batch-row groups x 32 H-col tiles

// Scratch (allocation-free rule: __device__ globals)
__device__ float  g_Z[(size_t)TT * BB * HH];    // Z = x@Wx + b, [t][b][h] (fp32, read by rec)
__device__ __half g_Sh[(size_t)TT * BB * HH];   // fp16 states row-major [t*64+b][h] (feeds out_kernel)
__device__ __half g_ST2h[2][4][HH * 16];        // fp16 transposed state ping-pong, [buf][r-group][h][16 b]
__device__ __half g_Wouth[HH * OO];             // fp16 Wout
__device__ __half g_Wxh[FF * HH];               // fp16 Wx
__device__ __half g_xh[(size_t)BB * FF * TT];   // fp16 x, [b][f][t]
__device__ unsigned g_flag[4 * 32 * 32];        // per-(r,c) generation flags, 128B apart

// ---------------------------------------------------------------- helpers
__device__ __forceinline__ void cp_async16(void* smem_dst, const void* gmem_src) {
    unsigned s = (unsigned)__cvta_generic_to_shared(smem_dst);
    asm volatile("cp.async.cg.shared.global [%0], [%1], 16;\n" :: "r"(s), "l"(gmem_src));
}
__device__ __forceinline__ void cp_commit() { asm volatile("cp.async.commit_group;\n"); }
template <int N> __device__ __forceinline__ void cp_wait() {
    asm volatile("cp.async.wait_group %0;\n" :: "n"(N));
}

__device__ __forceinline__ void mbar_init(uint32_t mb, uint32_t count) {
    asm volatile("mbarrier.init.shared.b64 [%0], %1;" :: "r"(mb), "r"(count) : "memory");
}
__device__ __forceinline__ void mbar_expect_tx(uint32_t mb, uint32_t bytes) {
    asm volatile("mbarrier.arrive.expect_tx.shared.b64 _, [%0], %1;" :: "r"(mb), "r"(bytes) : "memory");
}
__device__ __forceinline__ void bulk_g2s(uint32_t dst_smem, const void* src, uint32_t bytes, uint32_t mb) {
    asm volatile("cp.async.bulk.shared::cluster.global.mbarrier::complete_tx::bytes [%0], [%1], %2, [%3];"
                 :: "r"(dst_smem), "l"(src), "r"(bytes), "r"(mb) : "memory");
}
__device__ __forceinline__ void mbar_wait(uint32_t mb, int ph) {
    asm volatile(
        "{\n\t"
        ".reg .pred P;\n\t"
        "W%=:\n\t"
        "mbarrier.try_wait.parity.acquire.cta.shared::cta.b64 P, [%0], %1, 0x989680;\n\t"
        "@P bra D%=;\n\t"
        "bra W%=;\n\t"
        "D%=:\n\t"
        "}" :: "r"(mb), "r"(ph) : "memory");
}

__device__ __forceinline__ unsigned ld_acq_gpu(const unsigned* p) {
    unsigned v;
    asm volatile("ld.acquire.gpu.global.u32 %0, [%1];" : "=r"(v) : "l"(p) : "memory");
    return v;
}
__device__ __forceinline__ void bar_named(int id, int cnt) {
    asm volatile("bar.sync %0, %1;" :: "r"(id), "r"(cnt) : "memory");
}

__device__ __forceinline__ void ldsm_x4(uint32_t& r0, uint32_t& r1, uint32_t& r2, uint32_t& r3, uint32_t addr) {
    asm volatile("ldmatrix.sync.aligned.m8n8.x4.shared.b16 {%0,%1,%2,%3}, [%4];"
                 : "=r"(r0), "=r"(r1), "=r"(r2), "=r"(r3) : "r"(addr));
}
__device__ __forceinline__ void ldsm_x4_trans(uint32_t& r0, uint32_t& r1, uint32_t& r2, uint32_t& r3, uint32_t addr) {
    asm volatile("ldmatrix.sync.aligned.m8n8.x4.trans.shared.b16 {%0,%1,%2,%3}, [%4];"
                 : "=r"(r0), "=r"(r1), "=r"(r2), "=r"(r3) : "r"(addr));
}
__device__ __forceinline__ void ldsm_x2_trans(uint32_t& r0, uint32_t& r1, uint32_t addr) {
    asm volatile("ldmatrix.sync.aligned.m8n8.x2.trans.shared.b16 {%0,%1}, [%2];"
                 : "=r"(r0), "=r"(r1) : "r"(addr));
}
__device__ __forceinline__ void mma16816(float& d0, float& d1, float& d2, float& d3,
                                         uint32_t a0, uint32_t a1, uint32_t a2, uint32_t a3,
                                         uint32_t b0, uint32_t b1) {
    asm volatile("mma.sync.aligned.m16n8k16.row.col.f32.f16.f16.f32 "
                 "{%0,%1,%2,%3}, {%4,%5,%6,%7}, {%8,%9}, {%0,%1,%2,%3};"
                 : "+f"(d0), "+f"(d1), "+f"(d2), "+f"(d3)
                 : "r"(a0), "r"(a1), "r"(a2), "r"(a3), "r"(b0), "r"(b1));
}

// ---------------------------------------------------------------- small prep kernels
__global__ void reset_kernel() {
    for (int i = threadIdx.x; i < 4 * 32 * 32; i += blockDim.x) g_flag[i] = 0u;
}
__global__ void wcvt_kernel(const float* __restrict__ Wout) {
    int i = blockIdx.x * 256 + threadIdx.x;
    g_Wouth[i] = __float2half_rn(Wout[i]);
}
__global__ void wxcvt_kernel(const float* __restrict__ Wx) {
    int i = blockIdx.x * 256 + threadIdx.x;
    g_Wxh[i] = __float2half_rn(Wx[i]);
}
__global__ void xcvt_kernel(const float* __restrict__ x) {
    size_t i = ((size_t)blockIdx.x * 256 + threadIdx.x) * 4;
    float4 v = *reinterpret_cast<const float4*>(x + i);
    __half2* p = reinterpret_cast<__half2*>(g_xh + i);
    p[0] = __floats2half2_rn(v.x, v.y);
    p[1] = __floats2half2_rn(v.z, v.w);
}

// ---------------------------------------------------------------- Kernel A: Z[t][b][h] = b[h] + sum_f x[b][f][t] * Wx[f][h]  (HMMA fp16)
__global__ void __launch_bounds__(256, 2) zmat_kernel(const float* __restrict__ bias) {
    extern __shared__ __half hsm[];
    __half* As = hsm;                 // [2][32][136]
    __half* Bs = hsm + 2 * 32 * 136;  // [2][32][136]
    int h0 = blockIdx.x * 128;
    int t0 = blockIdx.y * 128;
    int b  = blockIdx.z;
    int tid = threadIdx.x;
    int w = tid >> 5, lane = tid & 31;

    float d[8][2][4];
    #pragma unroll
    for (int mt = 0; mt < 8; mt++)
        #pragma unroll
        for (int nt = 0; nt < 2; nt++)
            #pragma unroll
            for (int j = 0; j < 4; j++) d[mt][nt][j] = 0.f;

    auto issue = [&](int ci, int buf) {
        int f0 = ci * 32;
        __half* Ad = As + buf * 4352;
        __half* Bd = Bs + buf * 4352;
        #pragma unroll
        for (int it = 0; it < 2; it++) {
            int idx = it * 256 + tid;
            int f = idx >> 4, sg = idx & 15;
            cp_async16(Ad + f * 136 + sg * 8, g_xh + ((size_t)b * FF + f0 + f) * TT + t0 + sg * 8);
            cp_async16(Bd + f * 136 + sg * 8, g_Wxh + (size_t)(f0 + f) * HH + h0 + sg * 8);
        }
        cp_commit();
    };

    int brow = ((lane >> 3) & 1) * 8 + (lane & 7);
    int arow = ((lane >> 4) & 1) * 8 + (lane & 7);
    int acol = ((lane >> 3) & 1) * 8;

    issue(0, 0);
    for (int ci = 0; ci < 8; ci++) {
        if (ci < 7) { issue(ci + 1, (ci + 1) & 1); cp_wait<1>(); }
        else cp_wait<0>();
        __syncthreads();
        uint32_t a_base = (uint32_t)__cvta_generic_to_shared(As + (ci & 1) * 4352);
        uint32_t b_base = (uint32_t)__cvta_generic_to_shared(Bs + (ci & 1) * 4352);
        #pragma unroll
        for (int kt = 0; kt < 2; kt++) {
            uint32_t Bf[2][2];
            #pragma unroll
            for (int nt = 0; nt < 2; nt++) {
                uint32_t baddr = b_base + (uint32_t)((kt * 16 + brow) * 136 + w * 16 + nt * 8) * 2;
                ldsm_x2_trans(Bf[nt][0], Bf[nt][1], baddr);
            }
            #pragma unroll
            for (int mt = 0; mt < 8; mt++) {
                uint32_t a0, a1, a2, a3;
                uint32_t aaddr = a_base + (uint32_t)((kt * 16 + arow) * 136 + mt * 16 + acol) * 2;
                ldsm_x4_trans(a0, a1, a2, a3, aaddr);
                mma16816(d[mt][0][0], d[mt][0][1], d[mt][0][2], d[mt][0][3],
                         a0, a1, a2, a3, Bf[0][0], Bf[0][1]);
                mma16816(d[mt][1][0], d[mt][1][1], d[mt][1][2], d[mt][1][3],
                         a0, a1, a2, a3, Bf[1][0], Bf[1][1]);
            }
        }
        __syncthreads();
    }

    int nc = (lane & 3) * 2;
    int mrow = lane >> 2;
    #pragma unroll
    for (int nt = 0; nt < 2; nt++) {
        int col = h0 + w * 16 + nt * 8 + nc;
        float2 bv = *reinterpret_cast<const float2*>(bias + col);
        #pragma unroll
        for (int mt = 0; mt < 8; mt++) {
            int ta = t0 + mt * 16 + mrow;
            int tb = ta + 8;
            *reinterpret_cast<float2*>(g_Z + ((size_t)ta * BB + b) * HH + col) =
                make_float2(d[mt][nt][0] + bv.x, d[mt][nt][1] + bv.y);
            *reinterpret_cast<float2*>(g_Z + ((size_t)tb * BB + b) * HH + col) =
                make_float2(d[mt][nt][2] + bv.x, d[mt][nt][3] + bv.y);
        }
    }
}

// ---------------------------------------------------------------- Kernel B: persistent recurrence — self-staging HMMA dataflow
// 128 CTAs: (r: 16 batch rows) x (c: 32 H cols). 256 threads, 8 compute warps.
// Warp w owns k in [128w, 128w+128): lanes 0-3 poll its 4 producer flags, lane 0 issues
// its own 8KB TMA into warp-private SMEM, private mbarrier, then ldsm+mma. No stager
// warps, no consumed barriers (warp-local WAR ordering).
__global__ void __launch_bounds__(256, 1) rnn_rec_kernel(const float* __restrict__ Wh) {
    extern __shared__ float smem[];
    // [0..16 floats): 8 mbarriers (one per warp)
    __half* wh_h = reinterpret_cast<__half*>(smem + 16);        // [1024][32] halfs (64KB), init-only
    __half* st_h = reinterpret_cast<__half*>(smem + 16 + 16384);// [1024][16] halfs (32KB)
    float*  red_s = smem + 16 + 16384 + 8192;                   // [8][512] floats (16KB)
    float*  fin   = red_s + 4096;                               // [16][33] floats
    uint32_t mbar0 = (uint32_t)__cvta_generic_to_shared(smem);
    uint32_t st_base = (uint32_t)__cvta_generic_to_shared(st_h);
    uint32_t wh_base = (uint32_t)__cvta_generic_to_shared(wh_h);

    int tid  = threadIdx.x;
    int wid  = tid >> 5, lane = tid & 31;
    int c = blockIdx.x & 31;                // column tile (32 cols)
    int r = blockIdx.x >> 5;                // batch row group (16 rows)
    int r16 = r * 16;

    if (tid == 0) {
        #pragma unroll
        for (int w2 = 0; w2 < 8; w2++) mbar_init(mbar0 + w2 * 8, 1);
    }
    // Wh tile -> fp16 SMEM [k][32]
    for (int i = tid; i < 32768; i += 256) {
        int k = i >> 5, n = i & 31;
        wh_h[i] = __float2half_rn(Wh[k * HH + c * 32 + n]);
    }
    __syncthreads();

    unsigned* myflag = &g_flag[(r * 32 + c) * 32];

    int w = wid;
    uint32_t mymb = mbar0 + w * 8;

    // Preload B fragments (Wh^T tiles) into registers: 8 k-tiles x 4 n-tiles x 2 regs.
    uint32_t Bf[8][4][2];
    {
        int brow = ((lane >> 3) & 1) * 8 + (lane & 7);
        #pragma unroll
        for (int kt = 0; kt < 8; kt++) {
            int krow = w * 128 + kt * 16 + brow;
            #pragma unroll
            for (int nt = 0; nt < 4; nt++) {
                uint32_t addr = wh_base + (uint32_t)(krow * 32 + nt * 8) * 2;
                ldsm_x2_trans(Bf[kt][nt][0], Bf[kt][nt][1], addr);
            }
        }
    }

    // A ldmatrix (x4.trans from [k][16b]) address pattern
    int arow = ((lane >> 4) & 1) * 8 + (lane & 7);
    int acol = ((lane >> 3) & 1) * 8;

    // producer flag for lanes 0-3: CTAs c' = w*4 + lane cover h in [c'*32, c'*32+32)
    const unsigned* pf = &g_flag[(r * 32 + w * 4 + (lane & 3)) * 32];

    // epilogue mapping: 2 outputs per thread
    int o  = tid * 2;
    int em = o >> 5, en = o & 31;
    int brow2 = r16 + em, hcol = c * 32 + en;
    int j2 = tid * 2;
    int hl = j2 >> 4, em2 = j2 & 15;

    // D-frag store mapping
    int m0 = lane >> 2;
    int nc = (lane & 3) * 2;

    float* zbase = g_Z + (size_t)brow2 * HH + hcol;

    for (int t = 0; t < TT; ++t) {
        float2 zq = *reinterpret_cast<const float2*>(zbase + (size_t)t * (BB * HH));

        float d[4][4];
        #pragma unroll
        for (int nt = 0; nt < 4; nt++)
            #pragma unroll
            for (int j = 0; j < 4; j++) d[nt][j] = 0.f;

        if (t > 0) {
            // self-stage: poll own 4 producers, then TMA own 128k x 16b slice (8KB)
            if (lane < 4) {
                while (ld_acq_gpu(pf) < (unsigned)t) { }
            }
            __syncwarp();
            if (lane == 0) {
                asm volatile("fence.proxy.async;" ::: "memory");
                const __half* src = g_ST2h[(t + 1) & 1][r] + w * 2048;   // 2048 halfs = 4KB? no: 128k*16b = 2048 halfs
                mbar_expect_tx(mymb, 4096u);
                uint32_t dst = (uint32_t)__cvta_generic_to_shared(st_h + w * 2048);
                bulk_g2s(dst, src, 4096u, mymb);
            }
            mbar_wait(mymb, (t - 1) & 1);
            #pragma unroll
            for (int kt = 0; kt < 8; kt++) {
                uint32_t a0, a1, a2, a3;
                uint32_t addr = st_base + (uint32_t)((w * 128 + kt * 16 + arow) * 16 + acol) * 2;
                ldsm_x4_trans(a0, a1, a2, a3, addr);
                #pragma unroll
                for (int nt = 0; nt < 4; nt++)
                    mma16816(d[nt][0], d[nt][1], d[nt][2], d[nt][3],
                             a0, a1, a2, a3, Bf[kt][nt][0], Bf[kt][nt][1]);
            }
        }

        // partials: red_s[w][m*32 + n]
        {
            float* rp = red_s + w * 512;
            #pragma unroll
            for (int nt = 0; nt < 4; nt++) {
                *reinterpret_cast<float2*>(rp + m0 * 32 + nt * 8 + nc)       = make_float2(d[nt][0], d[nt][1]);
                *reinterpret_cast<float2*>(rp + (m0 + 8) * 32 + nt * 8 + nc) = make_float2(d[nt][2], d[nt][3]);
            }
        }
        bar_named(1, 256);
        float s0, s1;
        {
            float2 v = make_float2(0.f, 0.f);
            #pragma unroll
            for (int ww = 0; ww < 8; ww++) {
                float2 p = *reinterpret_cast<const float2*>(red_s + ww * 512 + o);
                v.x += p.x; v.y += p.y;
            }
            s0 = tanhf(zq.x + v.x);
            s1 = tanhf(zq.y + v.y);
            fin[em * 33 + en]     = s0;
            fin[em * 33 + en + 1] = s1;
        }
        bar_named(1, 256);
        {
            // coalesced transposed fp16 state store
            float a  = fin[em2 * 33 + hl];
            float b2 = fin[(em2 + 1) * 33 + hl];
            __half2* stp = reinterpret_cast<__half2*>(g_ST2h[t & 1][r] + (size_t)(c * 32 + hl) * 16 + em2);
            *stp = __floats2half2_rn(a, b2);
        }
        bar_named(1, 256);    // all state stores ordered before release
        if (tid == 0) {
            asm volatile("fence.acq_rel.gpu;" ::: "memory");
            unsigned g = (unsigned)(t + 1);
            asm volatile("st.relaxed.gpu.global.u32 [%0], %1;" :: "l"(myflag), "r"(g) : "memory");
        }
        // fp16 row-major states for out_kernel (off inter-CTA critical path)
        __half2* shp = reinterpret_cast<__half2*>(g_Sh + ((size_t)t * BB + brow2) * HH + hcol);
        *shp = __floats2half2_rn(s0, s1);
    }
}

// ---------------------------------------------------------------- Kernel C: out = S(fp16) @ Wout(fp16) + bout, HMMA
__global__ void __launch_bounds__(256, 1) out_kernel(const float* __restrict__ bout,
                                                     float* __restrict__ out) {
    extern __shared__ __half hsm[];
    __half* As = hsm;                 // [2][128][40]
    __half* Bs = hsm + 2 * 128 * 40;  // [2][32][136]
    int o0 = blockIdx.x * 128;
    int r0 = blockIdx.y * 128;
    int tid = threadIdx.x;
    int w = tid >> 5, lane = tid & 31;

    float d[8][2][4];
    #pragma unroll
    for (int mt = 0; mt < 8; mt++)
        #pragma unroll
        for (int nt = 0; nt < 2; nt++)
            #pragma unroll
            for (int j = 0; j < 4; j++) d[mt][nt][j] = 0.f;

    auto issue = [&](int ci, int buf) {
        int f0 = ci * 32;
        __half* Ad = As + buf * 5120;
        __half* Bd = Bs + buf * 4352;
        #pragma unroll
        for (int it = 0; it < 2; it++) {
            int idx = it * 256 + tid;
            int row = idx >> 2, seg = idx & 3;
            cp_async16(Ad + row * 40 + seg * 8, g_Sh + (size_t)(r0 + row) * HH + f0 + seg * 8);
            int kr = idx >> 4, sg = idx & 15;
            cp_async16(Bd + kr * 136 + sg * 8, g_Wouth + (size_t)(f0 + kr) * OO + o0 + sg * 8);
        }
        cp_commit();
    };

    int brow = ((lane >> 3) & 1) * 8 + (lane & 7);
    int amr = lane & 15;
    int akc = (lane >> 4) * 8;

    issue(0, 0);
    for (int ci = 0; ci < 32; ci++) {
        if (ci < 31) { issue(ci + 1, (ci + 1) & 1); cp_wait<1>(); }
        else cp_wait<0>();
        __syncthreads();
        const __half* Ac = As + (ci & 1) * 5120;
        const __half* Bc = Bs + (ci & 1) * 4352;
        uint32_t a_base = (uint32_t)__cvta_generic_to_shared(Ac);
        uint32_t b_base = (uint32_t)__cvta_generic_to_shared(Bc);
        #pragma unroll
        for (int kt = 0; kt < 2; kt++) {
            uint32_t Bf[2][2];
            #pragma unroll
            for (int nt = 0; nt < 2; nt++) {
                uint32_t baddr = b_base + (uint32_t)((kt * 16 + brow) * 136 + w * 16 + nt * 8) * 2;
                ldsm_x2_trans(Bf[nt][0], Bf[nt][1], baddr);
            }
            #pragma unroll
            for (int mt = 0; mt < 8; mt++) {
                uint32_t a0, a1, a2, a3;
                uint32_t aaddr = a_base + (uint32_t)((mt * 16 + amr) * 40 + kt * 16 + akc) * 2;
                ldsm_x4(a0, a1, a2, a3, aaddr);
                mma16816(d[mt][0][0], d[mt][0][1], d[mt][0][2], d[mt][0][3],
                         a0, a1, a2, a3, Bf[0][0], Bf[0][1]);
                mma16816(d[mt][1][0], d[mt][1][1], d[mt][1][2], d[mt][1][3],
                         a0, a1, a2, a3, Bf[1][0], Bf[1][1]);
            }
        }
        __syncthreads();
    }

    int nc = (lane & 3) * 2;
    int mrow = lane >> 2;
    #pragma unroll
    for (int nt = 0; nt < 2; nt++) {
        int col = o0 + w * 16 + nt * 8 + nc;
        float2 bv = *reinterpret_cast<const float2*>(bout + col);
        #pragma unroll
        for (int mt = 0; mt < 8; mt++) {
            int g0 = r0 + mt * 16 + mrow;
            int g1 = g0 + 8;
            int t0r = g0 >> 6, b0r = g0 & 63;
            int t1r = g1 >> 6, b1r = g1 & 63;
            *reinterpret_cast<float2*>(out + (size_t)b0r * (TT * OO) + t0r * OO + col) =
                make_float2(d[mt][nt][0] + bv.x, d[mt][nt][1] + bv.y);
            *reinterpret_cast<float2*>(out + (size_t)b1r * (TT * OO) + t1r * OO + col) =
                make_float2(d[mt][nt][2] + bv.x, d[mt][nt][3] + bv.y);
        }
    }
}

// ---------------------------------------------------------------- launch
extern "C" void kernel_launch(void* const* d_in, const int* in_sizes, int n_in,
                              void* d_out, int out_size) {
    const float* x    = (const float*)d_in[0];   // (B,F,T)
    const float* Wx   = (const float*)d_in[1];   // (F,H)
    const float* Wh   = (const float*)d_in[2];   // (H,H)
    const float* bv   = (const float*)d_in[3];   // (H,)
    const float* Wout = (const float*)d_in[4];   // (H,O)
    const float* bo   = (const float*)d_in[5];   // (O,)
    float* out = (float*)d_out;                  // (B,T,O)

    (void)in_sizes; (void)n_in; (void)out_size;

    // Phase 0: reset flags + fp16 conversions (x, Wx, Wout)
    reset_kernel<<<1, 256>>>();
    wcvt_kernel<<<(HH * OO) / 256, 256>>>(Wout);
    wxcvt_kernel<<<(FF * HH) / 256, 256>>>(Wx);
    xcvt_kernel<<<(int)(((size_t)BB * FF * TT) / 1024), 256>>>(x);

    // Phase 1: Z = x@Wx + b (HMMA fp16, 128x128 tiles, 2 CTAs/SM)
    size_t zsm = (size_t)(2 * 32 * 136 * 2) * sizeof(__half);   // 34816 B
    cudaFuncSetAttribute(zmat_kernel, cudaFuncAttributeMaxDynamicSharedMemorySize, (int)zsm);
    dim3 ga(HH / 128, TT / 128, BB);
    zmat_kernel<<<ga, 256, zsm>>>(bv);

    // Phase 2: persistent recurrence (self-staging HMMA dataflow, 256 threads)
    size_t dyn = (size_t)(16 + 16384 + 8192 + 4096 + 528) * sizeof(float);  // 116864 B
    cudaFuncSetAttribute(rnn_rec_kernel, cudaFuncAttributeMaxDynamicSharedMemorySize, 232448);
    rnn_rec_kernel<<<NB, 256, dyn>>>(Wh);

    // Phase 3: output projection (HMMA fp16, 128x128 tiles)
    size_t osm = (2 * 128 * 40 + 2 * 32 * 136) * sizeof(__half);  // 37888 B
    cudaFuncSetAttribute(out_kernel, cudaFuncAttributeMaxDynamicSharedMemorySize, (int)osm);
    dim3 gc(OO / 128, (TT * BB) / 128);   // n-inner for A-tile L2 reuse
    out_kernel<<<gc, 256, osm>>>(bo, out);
}